// round 2
// baseline (speedup 1.0000x reference)
#include <cuda_runtime.h>
#include <math.h>

// Problem constants (fixed shapes for MOELayer_53772990545994)
#define SDIM 4096      // S = B*T tokens
#define MDIM 1024      // model dim
#define EDIM 8         // experts
#define FDIM 4096      // ffn dim
#define CAP  1024      // capacity = 2*S/E

// ---------------- scratch (device globals; no allocation allowed) ----------
__device__ float g_gates[SDIM * EDIM];          // softmax gates per token
__device__ int   g_idx1[SDIM], g_idx2[SDIM];
__device__ int   g_loc1[SDIM], g_loc2[SDIM];
__device__ float g_g1raw[SDIM], g_g2raw[SDIM];  // pre-renorm gate values
__device__ float g_g1[SDIM], g_g2[SDIM];        // final combine weights
__device__ int   g_slot[EDIM * CAP];            // slot -> token id (-1 empty)
__device__ float g_h [(size_t)EDIM * CAP * FDIM];   // 128 MB: relu(disp @ w1)
__device__ float g_eo[(size_t)EDIM * CAP * MDIM];   // 32 MB:  h @ w2

// ---------------- 1) gating: logits, softmax, top-2 ------------------------
// one warp per token; 8 warps per block
__global__ void gate_kernel(const float* __restrict__ x,
                            const float* __restrict__ wg) {
    int warp = (blockIdx.x * blockDim.x + threadIdx.x) >> 5;
    int lane = threadIdx.x & 31;
    if (warp >= SDIM) return;
    const float* xr = x + (size_t)warp * MDIM;

    float acc[EDIM];
#pragma unroll
    for (int e = 0; e < EDIM; e++) acc[e] = 0.f;

    for (int m = lane; m < MDIM; m += 32) {
        float xv = xr[m];
        const float4* w4 = (const float4*)(wg + (size_t)m * EDIM);
        float4 a = w4[0], b = w4[1];
        acc[0] += xv * a.x; acc[1] += xv * a.y;
        acc[2] += xv * a.z; acc[3] += xv * a.w;
        acc[4] += xv * b.x; acc[5] += xv * b.y;
        acc[6] += xv * b.z; acc[7] += xv * b.w;
    }
#pragma unroll
    for (int o = 16; o > 0; o >>= 1)
#pragma unroll
        for (int e = 0; e < EDIM; e++)
            acc[e] += __shfl_xor_sync(0xffffffffu, acc[e], o);

    if (lane == 0) {
        // softmax over 8 logits
        float mx = acc[0];
#pragma unroll
        for (int e = 1; e < EDIM; e++) mx = fmaxf(mx, acc[e]);
        float p[EDIM], sum = 0.f;
#pragma unroll
        for (int e = 0; e < EDIM; e++) { p[e] = expf(acc[e] - mx); sum += p[e]; }
        float inv = 1.f / sum;
#pragma unroll
        for (int e = 0; e < EDIM; e++) {
            p[e] *= inv;
            g_gates[warp * EDIM + e] = p[e];
        }
        // top-1 on logits (== top-1 on gates), first occurrence wins
        int i1 = 0;
#pragma unroll
        for (int e = 1; e < EDIM; e++) if (acc[e] > acc[i1]) i1 = e;
        // top-2: argmax over logits with i1 masked
        int i2 = (i1 == 0) ? 1 : 0;
#pragma unroll
        for (int e = 0; e < EDIM; e++)
            if (e != i1 && acc[e] > acc[i2]) i2 = e;
        g_idx1[warp] = i1; g_idx2[warp] = i2;
        g_g1raw[warp] = p[i1]; g_g2raw[warp] = p[i2];
    }
}

// ---------------- 2) sequential-semantics scan (single block, 8 warps) -----
// warp e computes per-expert cumulative positions via ballot prefix.
__global__ void scan_kernel(float* laux_ptr) {
    __shared__ int   sCnt1[EDIM];
    __shared__ float sGsum[EDIM];
    int w    = threadIdx.x >> 5;   // expert id (blockDim = 256 => 8 warps)
    int lane = threadIdx.x & 31;
    unsigned ltmask = (1u << lane) - 1u;

    // pass 1: loc1 = cumsum(mask1) - 1 per expert (pre-drop)
    int base = 0;
    for (int s0 = 0; s0 < SDIM; s0 += 32) {
        int s = s0 + lane;
        bool m = (g_idx1[s] == w);
        unsigned bal = __ballot_sync(0xffffffffu, m);
        if (m) g_loc1[s] = base + __popc(bal & ltmask);
        base += __popc(bal);
    }
    if (lane == 0) sCnt1[w] = base;   // pre-drop top-1 count (used for loc2 offset AND l_aux)
    __syncthreads();

    // pass 2: loc2 = cumsum(mask2) - 1 + count1_total
    int base2 = sCnt1[w];
    for (int s0 = 0; s0 < SDIM; s0 += 32) {
        int s = s0 + lane;
        bool m = (g_idx2[s] == w);
        unsigned bal = __ballot_sync(0xffffffffu, m);
        if (m) g_loc2[s] = base2 + __popc(bal & ltmask);
        base2 += __popc(bal);
    }

    // deterministic per-expert gate sums for l_aux
    float acc = 0.f;
    for (int s = lane; s < SDIM; s += 32) acc += g_gates[s * EDIM + w];
#pragma unroll
    for (int o = 16; o > 0; o >>= 1) acc += __shfl_xor_sync(0xffffffffu, acc, o);
    if (lane == 0) sGsum[w] = acc;
    __syncthreads();

    if (threadIdx.x == 0 && laux_ptr != nullptr) {
        float l = 0.f;
#pragma unroll
        for (int e = 0; e < EDIM; e++) l += sGsum[e] * (float)sCnt1[e];
        // l_aux = mean_e(me*ce) * E^2 = E * sum(gsum*cnt1) / S^2
        *laux_ptr = l * (float)EDIM / ((float)SDIM * (float)SDIM);
    }
}

// ---------------- 3) slot init + finalize (drops, renorm, scatter) ---------
__global__ void init_slot_kernel() {
    int i = blockIdx.x * blockDim.x + threadIdx.x;
    if (i < EDIM * CAP) g_slot[i] = -1;
}

__global__ void finalize_kernel() {
    int s = blockIdx.x * blockDim.x + threadIdx.x;
    if (s >= SDIM) return;
    int l1 = g_loc1[s], l2 = g_loc2[s];
    int i1 = g_idx1[s], i2 = g_idx2[s];
    bool k1 = (l1 < CAP), k2 = (l2 < CAP);
    float g1s = k1 ? g_g1raw[s] : 0.f;
    float g2s = k2 ? g_g2raw[s] : 0.f;
    float den = g1s + g2s;
    if (den < 1e-9f) den = 1e-9f;
    g_g1[s] = g1s / den;
    g_g2[s] = g2s / den;
    if (k1) g_slot[i1 * CAP + l1] = s;
    if (k2) g_slot[i2 * CAP + l2] = s;
}

// ---------------- 4) per-expert SGEMM, 128x128x8 tile, 8x8/thread ----------
// GATHER=true : A row r = x[slot_token[e][r]] (zeros if empty), relu on store -> g_h
// GATHER=false: A = g_h[e], plain store -> g_eo
template<int KDIM, int NDIM, bool GATHER>
__global__ __launch_bounds__(256) void sgemm_kernel(const float* __restrict__ X,
                                                    const float* __restrict__ W) {
    const int e    = blockIdx.z;
    const int row0 = blockIdx.y * 128;
    const int col0 = blockIdx.x * 128;
    const float* B = W + (size_t)e * KDIM * NDIM;
    float* Cp = GATHER ? (g_h  + (size_t)e * CAP * NDIM)
                       : (g_eo + (size_t)e * CAP * NDIM);

    __shared__ float As[8][128];
    __shared__ float Bs[8][128];
    __shared__ int   stok[128];

    const int tid = threadIdx.x;
    if (GATHER && tid < 128) stok[tid] = g_slot[e * CAP + row0 + tid];
    __syncthreads();

    const int tx = tid & 15, ty = tid >> 4;
    const int arow = tid >> 1;          // A-tile row this thread loads
    const int akq  = (tid & 1) * 4;     // k-offset within 8
    const int bk   = tid >> 5;          // B-tile k-row
    const int bn   = (tid & 31) * 4;    // B-tile col offset

    const float* arp;
    if (GATHER) {
        int tok = stok[arow];
        arp = (tok >= 0) ? (X + (size_t)tok * KDIM) : nullptr;
    } else {
        arp = g_h + (size_t)e * CAP * KDIM + (size_t)(row0 + arow) * KDIM;
    }

    float acc[8][8];
#pragma unroll
    for (int i = 0; i < 8; i++)
#pragma unroll
        for (int j = 0; j < 8; j++) acc[i][j] = 0.f;

    for (int k0 = 0; k0 < KDIM; k0 += 8) {
        float4 av = make_float4(0.f, 0.f, 0.f, 0.f);
        if (!GATHER || arp) av = *(const float4*)(arp + k0 + akq);
        float4 bv = *(const float4*)(B + (size_t)(k0 + bk) * NDIM + col0 + bn);
        __syncthreads();
        As[akq + 0][arow] = av.x;
        As[akq + 1][arow] = av.y;
        As[akq + 2][arow] = av.z;
        As[akq + 3][arow] = av.w;
        *(float4*)&Bs[bk][bn] = bv;
        __syncthreads();
#pragma unroll
        for (int k = 0; k < 8; k++) {
            float a[8], b[8];
            *(float4*)(a)     = *(const float4*)&As[k][ty * 8];
            *(float4*)(a + 4) = *(const float4*)&As[k][ty * 8 + 4];
            *(float4*)(b)     = *(const float4*)&Bs[k][tx * 8];
            *(float4*)(b + 4) = *(const float4*)&Bs[k][tx * 8 + 4];
#pragma unroll
            for (int i = 0; i < 8; i++)
#pragma unroll
                for (int j = 0; j < 8; j++)
                    acc[i][j] += a[i] * b[j];
        }
    }

#pragma unroll
    for (int i = 0; i < 8; i++) {
        float* cr = Cp + (size_t)(row0 + ty * 8 + i) * NDIM + col0 + tx * 8;
        float v[8];
#pragma unroll
        for (int j = 0; j < 8; j++)
            v[j] = GATHER ? fmaxf(acc[i][j], 0.f) : acc[i][j];
        *(float4*)(cr)     = make_float4(v[0], v[1], v[2], v[3]);
        *(float4*)(cr + 4) = make_float4(v[4], v[5], v[6], v[7]);
    }
}

// ---------------- 5) combine: out[s] = g1*eo[e1,l1] + g2*eo[e2,l2] ---------
__global__ void combine_kernel(float* __restrict__ out) {
    int s = blockIdx.x;
    int t = threadIdx.x;  // 256 threads * float4 = 1024 = MDIM
    float g1 = g_g1[s], g2 = g_g2[s];
    int i1 = g_idx1[s], i2 = g_idx2[s];
    int l1 = g_loc1[s], l2 = g_loc2[s];
    bool k1 = (l1 < CAP), k2 = (l2 < CAP);

    float4 r = make_float4(0.f, 0.f, 0.f, 0.f);
    if (k1) {
        const float4* p = (const float4*)(g_eo + ((size_t)i1 * CAP + l1) * MDIM);
        float4 v = p[t];
        r.x += g1 * v.x; r.y += g1 * v.y; r.z += g1 * v.z; r.w += g1 * v.w;
    }
    if (k2) {
        const float4* p = (const float4*)(g_eo + ((size_t)i2 * CAP + l2) * MDIM);
        float4 v = p[t];
        r.x += g2 * v.x; r.y += g2 * v.y; r.z += g2 * v.z; r.w += g2 * v.w;
    }
    ((float4*)(out + (size_t)s * MDIM))[t] = r;
}

// ---------------- launch ----------------------------------------------------
extern "C" void kernel_launch(void* const* d_in, const int* in_sizes, int n_in,
                              void* d_out, int out_size) {
    const float* x  = (const float*)d_in[0];
    const float* wg = (const float*)d_in[1];
    const float* w1 = (const float*)d_in[2];
    const float* w2 = (const float*)d_in[3];
    float* out = (float*)d_out;
    float* laux_ptr = (out_size > SDIM * MDIM) ? (out + (size_t)SDIM * MDIM) : nullptr;

    gate_kernel<<<SDIM / 8, 256>>>(x, wg);
    scan_kernel<<<1, 256>>>(laux_ptr);
    init_slot_kernel<<<(EDIM * CAP + 255) / 256, 256>>>();
    finalize_kernel<<<SDIM / 256, 256>>>();
    // GEMM1: [C,M] @ [M,F] -> relu -> g_h   (gathered A rows from x)
    sgemm_kernel<MDIM, FDIM, true><<<dim3(FDIM / 128, CAP / 128, EDIM), 256>>>(x, w1);
    // GEMM2: [C,F] @ [F,M] -> g_eo
    sgemm_kernel<FDIM, MDIM, false><<<dim3(MDIM / 128, CAP / 128, EDIM), 256>>>(nullptr, w2);
    combine_kernel<<<SDIM, 256>>>(out);
}

// round 11
// speedup vs baseline: 1.7404x; 1.7404x over previous
#include <cuda_runtime.h>
#include <cuda_bf16.h>
#include <math.h>
#include <stdint.h>

// Problem constants (fixed shapes for MOELayer_53772990545994)
#define SDIM 4096      // S = B*T tokens
#define MDIM 1024      // model dim
#define EDIM 8         // experts
#define FDIM 4096      // ffn dim
#define CAP  1024      // capacity = 2*S/E

// ======================= helpers ===========================================
__device__ __forceinline__ uint32_t smem_u32(const void* p) {
    uint32_t a;
    asm("{ .reg .u64 t; cvta.to.shared.u64 t, %1; cvt.u32.u64 %0, t; }"
        : "=r"(a) : "l"(p));
    return a;
}
__device__ __forceinline__ void cp_async16(uint32_t saddr, const void* g) {
    asm volatile("cp.async.cg.shared.global [%0], [%1], 16;"
                 :: "r"(saddr), "l"(g) : "memory");
}
#define CP_COMMIT() asm volatile("cp.async.commit_group;" ::: "memory")
#define CP_WAIT1()  asm volatile("cp.async.wait_group 1;" ::: "memory")

__device__ __forceinline__ uint32_t lds32(uint32_t a) {
    uint32_t v;
    asm volatile("ld.shared.b32 %0, [%1];" : "=r"(v) : "r"(a));
    return v;
}
__device__ __forceinline__ void mma16816(float* c, const uint32_t* a, const uint32_t* b) {
    asm volatile("mma.sync.aligned.m16n8k16.row.col.f32.bf16.bf16.f32 "
                 "{%0,%1,%2,%3}, {%4,%5,%6,%7}, {%8,%9}, {%0,%1,%2,%3};"
                 : "+f"(c[0]), "+f"(c[1]), "+f"(c[2]), "+f"(c[3])
                 : "r"(a[0]), "r"(a[1]), "r"(a[2]), "r"(a[3]),
                   "r"(b[0]), "r"(b[1]));
}

// ======================= scratch (device globals) ===========================
// NOTE: these symbols are ONLY referenced from device code. Passing them as
// kernel arguments from host code hands the kernel a host shadow address.
__device__ float g_gates[SDIM * EDIM];
__device__ int   g_idx1[SDIM], g_idx2[SDIM];
__device__ int   g_loc1[SDIM], g_loc2[SDIM];
__device__ float g_g1raw[SDIM], g_g2raw[SDIM];
__device__ float g_g1[SDIM], g_g2[SDIM];
__device__ int   g_slot[EDIM * CAP];
// bf16 hi/lo operand storage
__device__ __nv_bfloat16 g_xa_hi[(size_t)EDIM * CAP * MDIM];
__device__ __nv_bfloat16 g_xa_lo[(size_t)EDIM * CAP * MDIM];
__device__ __nv_bfloat16 g_w1t_hi[(size_t)EDIM * FDIM * MDIM];  // [e][f][m]
__device__ __nv_bfloat16 g_w1t_lo[(size_t)EDIM * FDIM * MDIM];
__device__ __nv_bfloat16 g_w2t_hi[(size_t)EDIM * MDIM * FDIM];  // [e][m][f]
__device__ __nv_bfloat16 g_w2t_lo[(size_t)EDIM * MDIM * FDIM];
__device__ __nv_bfloat16 g_h_hi[(size_t)EDIM * CAP * FDIM];
__device__ __nv_bfloat16 g_h_lo[(size_t)EDIM * CAP * FDIM];
__device__ float g_eo[(size_t)EDIM * CAP * MDIM];

// ======================= 1) gating ==========================================
__global__ void gate_kernel(const float* __restrict__ x,
                            const float* __restrict__ wg) {
    int warp = (blockIdx.x * blockDim.x + threadIdx.x) >> 5;
    int lane = threadIdx.x & 31;
    if (warp >= SDIM) return;
    const float* xr = x + (size_t)warp * MDIM;

    float acc[EDIM];
#pragma unroll
    for (int e = 0; e < EDIM; e++) acc[e] = 0.f;
    for (int m = lane; m < MDIM; m += 32) {
        float xv = xr[m];
        const float4* w4 = (const float4*)(wg + (size_t)m * EDIM);
        float4 a = w4[0], b = w4[1];
        acc[0] += xv * a.x; acc[1] += xv * a.y;
        acc[2] += xv * a.z; acc[3] += xv * a.w;
        acc[4] += xv * b.x; acc[5] += xv * b.y;
        acc[6] += xv * b.z; acc[7] += xv * b.w;
    }
#pragma unroll
    for (int o = 16; o > 0; o >>= 1)
#pragma unroll
        for (int e = 0; e < EDIM; e++)
            acc[e] += __shfl_xor_sync(0xffffffffu, acc[e], o);

    if (lane == 0) {
        float mx = acc[0];
#pragma unroll
        for (int e = 1; e < EDIM; e++) mx = fmaxf(mx, acc[e]);
        float p[EDIM], sum = 0.f;
#pragma unroll
        for (int e = 0; e < EDIM; e++) { p[e] = expf(acc[e] - mx); sum += p[e]; }
        float inv = 1.f / sum;
#pragma unroll
        for (int e = 0; e < EDIM; e++) {
            p[e] *= inv;
            g_gates[warp * EDIM + e] = p[e];
        }
        int i1 = 0;
#pragma unroll
        for (int e = 1; e < EDIM; e++) if (acc[e] > acc[i1]) i1 = e;
        int i2 = (i1 == 0) ? 1 : 0;
#pragma unroll
        for (int e = 0; e < EDIM; e++)
            if (e != i1 && acc[e] > acc[i2]) i2 = e;
        g_idx1[warp] = i1; g_idx2[warp] = i2;
        g_g1raw[warp] = p[i1]; g_g2raw[warp] = p[i2];
    }
}

// ======================= 2) scan (single block) =============================
__global__ void scan_kernel(float* laux_ptr) {
    __shared__ int   sCnt1[EDIM];
    __shared__ float sGsum[EDIM];
    int w    = threadIdx.x >> 5;
    int lane = threadIdx.x & 31;
    unsigned ltmask = (1u << lane) - 1u;

    int base = 0;
    for (int s0 = 0; s0 < SDIM; s0 += 32) {
        int s = s0 + lane;
        bool m = (g_idx1[s] == w);
        unsigned bal = __ballot_sync(0xffffffffu, m);
        if (m) g_loc1[s] = base + __popc(bal & ltmask);
        base += __popc(bal);
    }
    if (lane == 0) sCnt1[w] = base;
    __syncthreads();

    int base2 = sCnt1[w];
    for (int s0 = 0; s0 < SDIM; s0 += 32) {
        int s = s0 + lane;
        bool m = (g_idx2[s] == w);
        unsigned bal = __ballot_sync(0xffffffffu, m);
        if (m) g_loc2[s] = base2 + __popc(bal & ltmask);
        base2 += __popc(bal);
    }

    float acc = 0.f;
    for (int s = lane; s < SDIM; s += 32) acc += g_gates[s * EDIM + w];
#pragma unroll
    for (int o = 16; o > 0; o >>= 1) acc += __shfl_xor_sync(0xffffffffu, acc, o);
    if (lane == 0) sGsum[w] = acc;
    __syncthreads();

    if (threadIdx.x == 0 && laux_ptr != nullptr) {
        float l = 0.f;
#pragma unroll
        for (int e = 0; e < EDIM; e++) l += sGsum[e] * (float)sCnt1[e];
        *laux_ptr = l * (float)EDIM / ((float)SDIM * (float)SDIM);
    }
}

// ======================= 3) slot init + finalize ============================
__global__ void init_slot_kernel() {
    int i = blockIdx.x * blockDim.x + threadIdx.x;
    if (i < EDIM * CAP) g_slot[i] = -1;
}

__global__ void finalize_kernel() {
    int s = blockIdx.x * blockDim.x + threadIdx.x;
    if (s >= SDIM) return;
    int l1 = g_loc1[s], l2 = g_loc2[s];
    int i1 = g_idx1[s], i2 = g_idx2[s];
    bool k1 = (l1 < CAP), k2 = (l2 < CAP);
    float g1s = k1 ? g_g1raw[s] : 0.f;
    float g2s = k2 ? g_g2raw[s] : 0.f;
    float den = g1s + g2s;
    if (den < 1e-9f) den = 1e-9f;
    g_g1[s] = g1s / den;
    g_g2[s] = g2s / den;
    if (k1) g_slot[i1 * CAP + l1] = s;
    if (k2) g_slot[i2 * CAP + l2] = s;
}

// ======================= 4) convert + gather x into bf16 hi/lo ==============
__global__ void convert_x_kernel(const float* __restrict__ x) {
    int slot = blockIdx.x;        // 0..8191
    int t = threadIdx.x;          // 256 threads * 4 elems
    int tok = g_slot[slot];
    float4 v = make_float4(0.f, 0.f, 0.f, 0.f);
    if (tok >= 0) v = ((const float4*)(x + (size_t)tok * MDIM))[t];
    __nv_bfloat16 h[4], l[4];
    float f[4] = {v.x, v.y, v.z, v.w};
#pragma unroll
    for (int i = 0; i < 4; i++) {
        h[i] = __float2bfloat16(f[i]);
        l[i] = __float2bfloat16(f[i] - __bfloat162float(h[i]));
    }
    size_t off = (size_t)slot * MDIM + t * 4;
    *(uint2*)&g_xa_hi[off] = *(uint2*)h;
    *(uint2*)&g_xa_lo[off] = *(uint2*)l;
}

// ======================= 5) weight transpose + split ========================
// in: [E][R][Cc] fp32 -> g_wXt hi/lo: [E][Cc][R] bf16.  WHICH: 1 -> w1t, 2 -> w2t.
template<int WHICH>
__global__ void transpose_split_kernel(const float* __restrict__ in,
                                       int R, int Cc) {
    __nv_bfloat16* oh = (WHICH == 1) ? g_w1t_hi : g_w2t_hi;
    __nv_bfloat16* ol = (WHICH == 1) ? g_w1t_lo : g_w2t_lo;
    __shared__ float t[32][33];
    int e = blockIdx.z;
    int c0 = blockIdx.x * 32, r0 = blockIdx.y * 32;
    const float* ip = in + (size_t)e * R * Cc;
    for (int i = threadIdx.y; i < 32; i += 8)
        t[i][threadIdx.x] = ip[(size_t)(r0 + i) * Cc + c0 + threadIdx.x];
    __syncthreads();
    size_t ob = (size_t)e * R * Cc;
    for (int i = threadIdx.y; i < 32; i += 8) {
        float v = t[threadIdx.x][i];
        __nv_bfloat16 h = __float2bfloat16(v);
        float lo = v - __bfloat162float(h);
        size_t o = ob + (size_t)(c0 + i) * R + r0 + threadIdx.x;
        oh[o] = h;
        ol[o] = __float2bfloat16(lo);
    }
}

// ======================= 6) bf16 HMMA GEMM (mma.sync) =======================
// C[128x128] per CTA = sum over 3 segments of A[128xK] @ B[128xK]^T:
//   seg0: Ahi*Bhi, seg1: Alo*Bhi, seg2: Ahi*Blo   (3-term fp32-split)
// 8 warps (2x4), warp tile 64x32, m16n8k16 HMMA.
// Fragments loaded with direct LDS.32 (documented mma thread->element map).
// 2-stage cp.async double buffer, 40960 B dynamic smem (<= 48KB default).
// Operand arrays are device globals resolved IN DEVICE CODE via FFN1.
#define BM 128
#define BN 128
#define BK 32
#define SROWB 80                      // 80B row stride -> conflict-free LDS.32
#define STAGE_BYTES (2 * 128 * SROWB) // A(10240) + B(10240) = 20480
#define B_SOFF (128 * SROWB)

template<int KDIM, int NTOT, bool FFN1>
__global__ __launch_bounds__(256) void mma_gemm_kernel() {
    extern __shared__ char smbuf[];
    const int tid  = threadIdx.x;
    const int wid  = tid >> 5;
    const int lane = tid & 31;
    const int e    = blockIdx.z;
    const int row0 = blockIdx.y * BM;
    const int col0 = blockIdx.x * BN;
    const int KI   = KDIM / BK;       // chunks per segment
    const int NK   = 3 * KI;

    const int wm = (wid >> 2) * 64;   // warp row offset within CTA tile
    const int wn = (wid & 3) * 32;    // warp col offset
    const int lq = lane >> 2;         // 0..7
    const int lr = lane & 3;          // 0..3

    uint32_t sbase = smem_u32(smbuf);

    // device-side symbol resolution (host must NOT pass these)
    const __nv_bfloat16* Ahi = FFN1 ? g_xa_hi  : g_h_hi;
    const __nv_bfloat16* Alo = FFN1 ? g_xa_lo  : g_h_lo;
    const __nv_bfloat16* Bhi = FFN1 ? g_w1t_hi : g_w2t_hi;
    const __nv_bfloat16* Blo = FFN1 ? g_w1t_lo : g_w2t_lo;

    const __nv_bfloat16* Ah = Ahi + ((size_t)e * CAP  + row0) * KDIM;
    const __nv_bfloat16* Al = Alo + ((size_t)e * CAP  + row0) * KDIM;
    const __nv_bfloat16* Bh = Bhi + ((size_t)e * NTOT + col0) * KDIM;
    const __nv_bfloat16* Bl = Blo + ((size_t)e * NTOT + col0) * KDIM;

    auto prefetch = [&](int p) {
        int seg = p / KI;
        int kk  = (p - seg * KI) * BK;
        const __nv_bfloat16* Ap = (seg == 1) ? Al : Ah;
        const __nv_bfloat16* Bp = (seg == 2) ? Bl : Bh;
        uint32_t sb = sbase + (uint32_t)(p & 1) * STAGE_BYTES;
#pragma unroll
        for (int c = tid; c < 1024; c += 256) {
            int r = (c >> 2) & 127;
            int q = c & 3;
            if (c < 512)
                cp_async16(sb + r * SROWB + q * 16,
                           Ap + (size_t)r * KDIM + kk + q * 8);
            else
                cp_async16(sb + B_SOFF + r * SROWB + q * 16,
                           Bp + (size_t)r * KDIM + kk + q * 8);
        }
    };

    float acc[4][4][4];
#pragma unroll
    for (int i = 0; i < 4; i++)
#pragma unroll
        for (int j = 0; j < 4; j++)
#pragma unroll
            for (int k = 0; k < 4; k++) acc[i][j][k] = 0.f;

    prefetch(0); CP_COMMIT();

    for (int i = 0; i < NK; i++) {
        if (i + 1 < NK) prefetch(i + 1);
        CP_COMMIT();
        CP_WAIT1();             // chunk i resident
        __syncthreads();

        uint32_t sb = sbase + (uint32_t)(i & 1) * STAGE_BYTES;
#pragma unroll
        for (int ks = 0; ks < 2; ks++) {
            uint32_t a[4][4], b[4][2];
#pragma unroll
            for (int mt = 0; mt < 4; mt++) {
                uint32_t ba = sb + (uint32_t)(wm + mt * 16 + lq) * SROWB
                            + ks * 32 + lr * 4;
                a[mt][0] = lds32(ba);
                a[mt][1] = lds32(ba + 8 * SROWB);
                a[mt][2] = lds32(ba + 16);
                a[mt][3] = lds32(ba + 8 * SROWB + 16);
            }
#pragma unroll
            for (int nt = 0; nt < 4; nt++) {
                uint32_t bb = sb + B_SOFF + (uint32_t)(wn + nt * 8 + lq) * SROWB
                            + ks * 32 + lr * 4;
                b[nt][0] = lds32(bb);
                b[nt][1] = lds32(bb + 16);
            }
#pragma unroll
            for (int mt = 0; mt < 4; mt++)
#pragma unroll
                for (int nt = 0; nt < 4; nt++)
                    mma16816(acc[mt][nt], a[mt], b[nt]);
        }
        __syncthreads();        // stage may be overwritten next iter
    }

    // epilogue: c0/c1 at (row=lq, col=lr*2), c2/c3 at row lq+8
#pragma unroll
    for (int mt = 0; mt < 4; mt++) {
#pragma unroll
        for (int half = 0; half < 2; half++) {
            int grow = row0 + wm + mt * 16 + lq + half * 8;
            size_t rowg = (size_t)e * CAP + grow;
#pragma unroll
            for (int nt = 0; nt < 4; nt++) {
                float v0 = acc[mt][nt][half * 2 + 0];
                float v1 = acc[mt][nt][half * 2 + 1];
                int gcol = col0 + wn + nt * 8 + lr * 2;
                if (FFN1) {
                    v0 = fmaxf(v0, 0.f); v1 = fmaxf(v1, 0.f);
                    __nv_bfloat16 h0 = __float2bfloat16(v0);
                    __nv_bfloat16 h1 = __float2bfloat16(v1);
                    __nv_bfloat16 l0 = __float2bfloat16(v0 - __bfloat162float(h0));
                    __nv_bfloat16 l1 = __float2bfloat16(v1 - __bfloat162float(h1));
                    __nv_bfloat162 hv; hv.x = h0; hv.y = h1;
                    __nv_bfloat162 lv; lv.x = l0; lv.y = l1;
                    *(__nv_bfloat162*)&g_h_hi[rowg * FDIM + gcol] = hv;
                    *(__nv_bfloat162*)&g_h_lo[rowg * FDIM + gcol] = lv;
                } else {
                    float2 o; o.x = v0; o.y = v1;
                    *(float2*)&g_eo[rowg * MDIM + gcol] = o;
                }
            }
        }
    }
}

// ======================= 7) combine =========================================
__global__ void combine_kernel(float* __restrict__ out) {
    int s = blockIdx.x;
    int t = threadIdx.x;
    float g1 = g_g1[s], g2 = g_g2[s];
    int i1 = g_idx1[s], i2 = g_idx2[s];
    int l1 = g_loc1[s], l2 = g_loc2[s];
    bool k1 = (l1 < CAP), k2 = (l2 < CAP);

    float4 r = make_float4(0.f, 0.f, 0.f, 0.f);
    if (k1) {
        const float4* p = (const float4*)(g_eo + ((size_t)i1 * CAP + l1) * MDIM);
        float4 v = p[t];
        r.x += g1 * v.x; r.y += g1 * v.y; r.z += g1 * v.z; r.w += g1 * v.w;
    }
    if (k2) {
        const float4* p = (const float4*)(g_eo + ((size_t)i2 * CAP + l2) * MDIM);
        float4 v = p[t];
        r.x += g2 * v.x; r.y += g2 * v.y; r.z += g2 * v.z; r.w += g2 * v.w;
    }
    ((float4*)(out + (size_t)s * MDIM))[t] = r;
}

// ======================= launch =============================================
extern "C" void kernel_launch(void* const* d_in, const int* in_sizes, int n_in,
                              void* d_out, int out_size) {
    const float* x  = (const float*)d_in[0];
    const float* wg = (const float*)d_in[1];
    const float* w1 = (const float*)d_in[2];
    const float* w2 = (const float*)d_in[3];
    float* out = (float*)d_out;
    float* laux_ptr = (out_size > SDIM * MDIM) ? (out + (size_t)SDIM * MDIM) : nullptr;

    const int DSMEM = 2 * STAGE_BYTES;   // 40960 <= 48KB default, no opt-in needed

    gate_kernel<<<SDIM / 8, 256>>>(x, wg);
    scan_kernel<<<1, 256>>>(laux_ptr);
    init_slot_kernel<<<(EDIM * CAP + 255) / 256, 256>>>();
    finalize_kernel<<<SDIM / 256, 256>>>();
    convert_x_kernel<<<EDIM * CAP, 256>>>(x);
    // w1 [e][M][F] -> g_w1t [e][F][M]
    transpose_split_kernel<1><<<dim3(FDIM / 32, MDIM / 32, EDIM), dim3(32, 8)>>>(
        w1, MDIM, FDIM);
    // w2 [e][F][M] -> g_w2t [e][M][F]
    transpose_split_kernel<2><<<dim3(MDIM / 32, FDIM / 32, EDIM), dim3(32, 8)>>>(
        w2, FDIM, MDIM);
    // GEMM1: [CAP x M] @ w1t^T -> relu -> g_h (bf16 hi/lo)
    mma_gemm_kernel<MDIM, FDIM, true>
        <<<dim3(FDIM / BN, CAP / BM, EDIM), 256, DSMEM>>>();
    // GEMM2: [CAP x F] @ w2t^T -> g_eo (fp32)
    mma_gemm_kernel<FDIM, MDIM, false>
        <<<dim3(MDIM / BN, CAP / BM, EDIM), 256, DSMEM>>>();
    combine_kernel<<<SDIM, 256>>>(out);
}

// round 12
// speedup vs baseline: 2.1322x; 1.2252x over previous
#include <cuda_runtime.h>
#include <cuda_bf16.h>
#include <math.h>
#include <stdint.h>

// Problem constants (fixed shapes for MOELayer_53772990545994)
#define SDIM 4096      // S = B*T tokens
#define MDIM 1024      // model dim
#define EDIM 8         // experts
#define FDIM 4096      // ffn dim
#define CAP  1024      // capacity = 2*S/E

// ======================= helpers ===========================================
__device__ __forceinline__ uint32_t smem_u32(const void* p) {
    uint32_t a;
    asm("{ .reg .u64 t; cvta.to.shared.u64 t, %1; cvt.u32.u64 %0, t; }"
        : "=r"(a) : "l"(p));
    return a;
}
__device__ __forceinline__ void cp_async16(uint32_t saddr, const void* g) {
    asm volatile("cp.async.cg.shared.global [%0], [%1], 16;"
                 :: "r"(saddr), "l"(g) : "memory");
}
#define CP_COMMIT() asm volatile("cp.async.commit_group;" ::: "memory")
#define CP_WAIT1()  asm volatile("cp.async.wait_group 1;" ::: "memory")

__device__ __forceinline__ void ldsm_x4(uint32_t* r, uint32_t a) {
    asm volatile("ldmatrix.sync.aligned.m8n8.x4.shared.b16 {%0,%1,%2,%3}, [%4];"
                 : "=r"(r[0]), "=r"(r[1]), "=r"(r[2]), "=r"(r[3]) : "r"(a));
}
__device__ __forceinline__ void mma16816(float* c, const uint32_t* a, const uint32_t* b) {
    asm volatile("mma.sync.aligned.m16n8k16.row.col.f32.bf16.bf16.f32 "
                 "{%0,%1,%2,%3}, {%4,%5,%6,%7}, {%8,%9}, {%0,%1,%2,%3};"
                 : "+f"(c[0]), "+f"(c[1]), "+f"(c[2]), "+f"(c[3])
                 : "r"(a[0]), "r"(a[1]), "r"(a[2]), "r"(a[3]),
                   "r"(b[0]), "r"(b[1]));
}

// ======================= scratch (device globals) ===========================
// NOTE: only referenced from device code (host sees shadow addresses).
__device__ float g_gates[SDIM * EDIM];
__device__ int   g_idx1[SDIM], g_idx2[SDIM];
__device__ int   g_loc1[SDIM], g_loc2[SDIM];
__device__ float g_g1raw[SDIM], g_g2raw[SDIM];
__device__ float g_g1[SDIM], g_g2[SDIM];
__device__ int   g_slot[EDIM * CAP];
__device__ __nv_bfloat16 g_xa_hi[(size_t)EDIM * CAP * MDIM];
__device__ __nv_bfloat16 g_xa_lo[(size_t)EDIM * CAP * MDIM];
__device__ __nv_bfloat16 g_w1t_hi[(size_t)EDIM * FDIM * MDIM];  // [e][f][m]
__device__ __nv_bfloat16 g_w1t_lo[(size_t)EDIM * FDIM * MDIM];
__device__ __nv_bfloat16 g_w2t_hi[(size_t)EDIM * MDIM * FDIM];  // [e][m][f]
__device__ __nv_bfloat16 g_w2t_lo[(size_t)EDIM * MDIM * FDIM];
__device__ __nv_bfloat16 g_h_hi[(size_t)EDIM * CAP * FDIM];
__device__ __nv_bfloat16 g_h_lo[(size_t)EDIM * CAP * FDIM];
__device__ float g_eo[(size_t)EDIM * CAP * MDIM];

// ======================= 1) gating ==========================================
__global__ void gate_kernel(const float* __restrict__ x,
                            const float* __restrict__ wg) {
    int warp = (blockIdx.x * blockDim.x + threadIdx.x) >> 5;
    int lane = threadIdx.x & 31;
    if (warp >= SDIM) return;
    const float* xr = x + (size_t)warp * MDIM;

    float acc[EDIM];
#pragma unroll
    for (int e = 0; e < EDIM; e++) acc[e] = 0.f;
    for (int m = lane; m < MDIM; m += 32) {
        float xv = xr[m];
        const float4* w4 = (const float4*)(wg + (size_t)m * EDIM);
        float4 a = w4[0], b = w4[1];
        acc[0] += xv * a.x; acc[1] += xv * a.y;
        acc[2] += xv * a.z; acc[3] += xv * a.w;
        acc[4] += xv * b.x; acc[5] += xv * b.y;
        acc[6] += xv * b.z; acc[7] += xv * b.w;
    }
#pragma unroll
    for (int o = 16; o > 0; o >>= 1)
#pragma unroll
        for (int e = 0; e < EDIM; e++)
            acc[e] += __shfl_xor_sync(0xffffffffu, acc[e], o);

    if (lane == 0) {
        float mx = acc[0];
#pragma unroll
        for (int e = 1; e < EDIM; e++) mx = fmaxf(mx, acc[e]);
        float p[EDIM], sum = 0.f;
#pragma unroll
        for (int e = 0; e < EDIM; e++) { p[e] = expf(acc[e] - mx); sum += p[e]; }
        float inv = 1.f / sum;
#pragma unroll
        for (int e = 0; e < EDIM; e++) {
            p[e] *= inv;
            g_gates[warp * EDIM + e] = p[e];
        }
        int i1 = 0;
#pragma unroll
        for (int e = 1; e < EDIM; e++) if (acc[e] > acc[i1]) i1 = e;
        int i2 = (i1 == 0) ? 1 : 0;
#pragma unroll
        for (int e = 0; e < EDIM; e++)
            if (e != i1 && acc[e] > acc[i2]) i2 = e;
        g_idx1[warp] = i1; g_idx2[warp] = i2;
        g_g1raw[warp] = p[i1]; g_g2raw[warp] = p[i2];
    }
}

// ======================= 2) scan (single block) =============================
__global__ void scan_kernel(float* laux_ptr) {
    __shared__ int   sCnt1[EDIM];
    __shared__ float sGsum[EDIM];
    int w    = threadIdx.x >> 5;
    int lane = threadIdx.x & 31;
    unsigned ltmask = (1u << lane) - 1u;

    int base = 0;
    for (int s0 = 0; s0 < SDIM; s0 += 32) {
        int s = s0 + lane;
        bool m = (g_idx1[s] == w);
        unsigned bal = __ballot_sync(0xffffffffu, m);
        if (m) g_loc1[s] = base + __popc(bal & ltmask);
        base += __popc(bal);
    }
    if (lane == 0) sCnt1[w] = base;
    __syncthreads();

    int base2 = sCnt1[w];
    for (int s0 = 0; s0 < SDIM; s0 += 32) {
        int s = s0 + lane;
        bool m = (g_idx2[s] == w);
        unsigned bal = __ballot_sync(0xffffffffu, m);
        if (m) g_loc2[s] = base2 + __popc(bal & ltmask);
        base2 += __popc(bal);
    }

    float acc = 0.f;
    for (int s = lane; s < SDIM; s += 32) acc += g_gates[s * EDIM + w];
#pragma unroll
    for (int o = 16; o > 0; o >>= 1) acc += __shfl_xor_sync(0xffffffffu, acc, o);
    if (lane == 0) sGsum[w] = acc;
    __syncthreads();

    if (threadIdx.x == 0 && laux_ptr != nullptr) {
        float l = 0.f;
#pragma unroll
        for (int e = 0; e < EDIM; e++) l += sGsum[e] * (float)sCnt1[e];
        *laux_ptr = l * (float)EDIM / ((float)SDIM * (float)SDIM);
    }
}

// ======================= 3) slot init + finalize ============================
__global__ void init_slot_kernel() {
    int i = blockIdx.x * blockDim.x + threadIdx.x;
    if (i < EDIM * CAP) g_slot[i] = -1;
}

__global__ void finalize_kernel() {
    int s = blockIdx.x * blockDim.x + threadIdx.x;
    if (s >= SDIM) return;
    int l1 = g_loc1[s], l2 = g_loc2[s];
    int i1 = g_idx1[s], i2 = g_idx2[s];
    bool k1 = (l1 < CAP), k2 = (l2 < CAP);
    float g1s = k1 ? g_g1raw[s] : 0.f;
    float g2s = k2 ? g_g2raw[s] : 0.f;
    float den = g1s + g2s;
    if (den < 1e-9f) den = 1e-9f;
    g_g1[s] = g1s / den;
    g_g2[s] = g2s / den;
    if (k1) g_slot[i1 * CAP + l1] = s;
    if (k2) g_slot[i2 * CAP + l2] = s;
}

// ======================= 4) convert + gather x into bf16 hi/lo ==============
__global__ void convert_x_kernel(const float* __restrict__ x) {
    int slot = blockIdx.x;        // 0..8191
    int t = threadIdx.x;          // 256 threads * 4 elems
    int tok = g_slot[slot];
    float4 v = make_float4(0.f, 0.f, 0.f, 0.f);
    if (tok >= 0) v = ((const float4*)(x + (size_t)tok * MDIM))[t];
    __nv_bfloat16 h[4], l[4];
    float f[4] = {v.x, v.y, v.z, v.w};
#pragma unroll
    for (int i = 0; i < 4; i++) {
        h[i] = __float2bfloat16(f[i]);
        l[i] = __float2bfloat16(f[i] - __bfloat162float(h[i]));
    }
    size_t off = (size_t)slot * MDIM + t * 4;
    *(uint2*)&g_xa_hi[off] = *(uint2*)h;
    *(uint2*)&g_xa_lo[off] = *(uint2*)l;
}

// ======================= 5) weight transpose + split ========================
// in: [E][R][Cc] fp32 -> g_wXt hi/lo: [E][Cc][R] bf16.  WHICH: 1 -> w1t, 2 -> w2t.
template<int WHICH>
__global__ void transpose_split_kernel(const float* __restrict__ in,
                                       int R, int Cc) {
    __nv_bfloat16* oh = (WHICH == 1) ? g_w1t_hi : g_w2t_hi;
    __nv_bfloat16* ol = (WHICH == 1) ? g_w1t_lo : g_w2t_lo;
    __shared__ float t[32][33];
    int e = blockIdx.z;
    int c0 = blockIdx.x * 32, r0 = blockIdx.y * 32;
    const float* ip = in + (size_t)e * R * Cc;
    for (int i = threadIdx.y; i < 32; i += 8)
        t[i][threadIdx.x] = ip[(size_t)(r0 + i) * Cc + c0 + threadIdx.x];
    __syncthreads();
    size_t ob = (size_t)e * R * Cc;
    for (int i = threadIdx.y; i < 32; i += 8) {
        float v = t[threadIdx.x][i];
        __nv_bfloat16 h = __float2bfloat16(v);
        float lo = v - __bfloat162float(h);
        size_t o = ob + (size_t)(c0 + i) * R + r0 + threadIdx.x;
        oh[o] = h;
        ol[o] = __float2bfloat16(lo);
    }
}

// ======================= 6) bf16 HMMA GEMM (mma.sync) =======================
// C[128x256] per CTA = sum over 3 segments of A[128xK] @ B[256xK]^T:
//   seg0: Ahi*Bhi, seg1: Alo*Bhi, seg2: Ahi*Blo   (3-term fp32-split)
// 8 warps (2x4), warp tile 64x64, m16n8k16 HMMA, ldmatrix.x4 fragments.
// BK=64 chunks, 3-stage cp.async pipeline, one __syncthreads per chunk.
// smem row stride 144B (9*16): ldmatrix banks (9r+c) mod 8 all distinct.
#define BM 128
#define BN 256
#define BK 64
#define NSTAGE 3
#define SROWB 144
#define A_BYTES (128 * SROWB)            // 18432
#define B_BYTES (256 * SROWB)            // 36864
#define STAGE_BYTES (A_BYTES + B_BYTES)  // 55296
#define B_SOFF A_BYTES
#define GEMM_DSMEM (NSTAGE * STAGE_BYTES) // 165888

template<int KDIM, int NTOT, bool FFN1>
__global__ __launch_bounds__(256, 1) void mma_gemm_kernel() {
    extern __shared__ char smbuf[];
    const int tid  = threadIdx.x;
    const int wid  = tid >> 5;
    const int lane = tid & 31;
    const int e    = blockIdx.z;
    const int row0 = blockIdx.y * BM;
    const int col0 = blockIdx.x * BN;
    const int KI   = KDIM / BK;       // chunks per segment
    const int NK   = 3 * KI;

    const int wm = (wid >> 2) * 64;   // warp row offset (2 groups)
    const int wn = (wid & 3) * 64;    // warp col offset (4 groups)
    const int lq = lane >> 2;         // 0..7
    const int lr = lane & 3;          // 0..3

    uint32_t sbase = smem_u32(smbuf);

    // device-side symbol resolution
    const __nv_bfloat16* Ahi = FFN1 ? g_xa_hi  : g_h_hi;
    const __nv_bfloat16* Alo = FFN1 ? g_xa_lo  : g_h_lo;
    const __nv_bfloat16* Bhi = FFN1 ? g_w1t_hi : g_w2t_hi;
    const __nv_bfloat16* Blo = FFN1 ? g_w1t_lo : g_w2t_lo;

    const __nv_bfloat16* Ah = Ahi + ((size_t)e * CAP  + row0) * KDIM;
    const __nv_bfloat16* Al = Alo + ((size_t)e * CAP  + row0) * KDIM;
    const __nv_bfloat16* Bh = Bhi + ((size_t)e * NTOT + col0) * KDIM;
    const __nv_bfloat16* Bl = Blo + ((size_t)e * NTOT + col0) * KDIM;

    // chunk p -> (segment, k-offset); A tile 128x64, B tile 256x64
    auto prefetch = [&](int p) {
        int seg = p / KI;
        int kk  = (p - seg * KI) * BK;
        const __nv_bfloat16* Ap = (seg == 1) ? Al : Ah;
        const __nv_bfloat16* Bp = (seg == 2) ? Bl : Bh;
        uint32_t sb = sbase + (uint32_t)(p % NSTAGE) * STAGE_BYTES;
#pragma unroll
        for (int c = tid; c < 3072; c += 256) {
            if (c < 1024) {                 // A: 128 rows x 8 16B-chunks
                int r = c >> 3, q = c & 7;
                cp_async16(sb + r * SROWB + q * 16,
                           Ap + (size_t)r * KDIM + kk + q * 8);
            } else {                        // B: 256 rows x 8 16B-chunks
                int c2 = c - 1024;
                int r = c2 >> 3, q = c2 & 7;
                cp_async16(sb + B_SOFF + r * SROWB + q * 16,
                           Bp + (size_t)r * KDIM + kk + q * 8);
            }
        }
    };

    float acc[4][8][4];
#pragma unroll
    for (int i = 0; i < 4; i++)
#pragma unroll
        for (int j = 0; j < 8; j++)
#pragma unroll
            for (int k = 0; k < 4; k++) acc[i][j][k] = 0.f;

    prefetch(0); CP_COMMIT();
    prefetch(1); CP_COMMIT();

    // per-thread intra-fragment offsets (constant over loop)
    const int a_row = lane & 15;            // +16B half select below
    const int a_half = (lane >> 4) << 4;
    const int b_grp = lane >> 3;            // 0..3
    const int b_row = (b_grp >> 1) * 8 + (lane & 7);
    const int b_half = (b_grp & 1) << 4;

    for (int i = 0; i < NK; i++) {
        CP_WAIT1();             // chunk i resident (chunk i+1 may be in flight)
        __syncthreads();        // all warps done reading stage (i-1)%3
        if (i + 2 < NK) prefetch(i + 2);
        CP_COMMIT();

        uint32_t sb = sbase + (uint32_t)(i % NSTAGE) * STAGE_BYTES;
#pragma unroll
        for (int ks = 0; ks < 4; ks++) {
            uint32_t a[4][4], bf[4][4];
#pragma unroll
            for (int mt = 0; mt < 4; mt++) {
                uint32_t addr = sb + (uint32_t)(wm + mt * 16 + a_row) * SROWB
                              + ks * 32 + a_half;
                ldsm_x4(a[mt], addr);
            }
#pragma unroll
            for (int np = 0; np < 4; np++) {   // covers nt=2np, 2np+1
                uint32_t addr = sb + B_SOFF
                              + (uint32_t)(wn + np * 16 + b_row) * SROWB
                              + ks * 32 + b_half;
                ldsm_x4(bf[np], addr);
            }
#pragma unroll
            for (int mt = 0; mt < 4; mt++)
#pragma unroll
                for (int nt = 0; nt < 8; nt++)
                    mma16816(acc[mt][nt], a[mt], &bf[nt >> 1][(nt & 1) * 2]);
        }
    }

    // epilogue: c0/c1 at (row=lq, col=lr*2), c2/c3 at row lq+8
#pragma unroll
    for (int mt = 0; mt < 4; mt++) {
#pragma unroll
        for (int half = 0; half < 2; half++) {
            int grow = row0 + wm + mt * 16 + lq + half * 8;
            size_t rowg = (size_t)e * CAP + grow;
#pragma unroll
            for (int nt = 0; nt < 8; nt++) {
                float v0 = acc[mt][nt][half * 2 + 0];
                float v1 = acc[mt][nt][half * 2 + 1];
                int gcol = col0 + wn + nt * 8 + lr * 2;
                if (FFN1) {
                    v0 = fmaxf(v0, 0.f); v1 = fmaxf(v1, 0.f);
                    __nv_bfloat16 h0 = __float2bfloat16(v0);
                    __nv_bfloat16 h1 = __float2bfloat16(v1);
                    __nv_bfloat16 l0 = __float2bfloat16(v0 - __bfloat162float(h0));
                    __nv_bfloat16 l1 = __float2bfloat16(v1 - __bfloat162float(h1));
                    __nv_bfloat162 hv; hv.x = h0; hv.y = h1;
                    __nv_bfloat162 lv; lv.x = l0; lv.y = l1;
                    *(__nv_bfloat162*)&g_h_hi[rowg * FDIM + gcol] = hv;
                    *(__nv_bfloat162*)&g_h_lo[rowg * FDIM + gcol] = lv;
                } else {
                    float2 o; o.x = v0; o.y = v1;
                    *(float2*)&g_eo[rowg * MDIM + gcol] = o;
                }
            }
        }
    }
}

// ======================= 7) combine =========================================
__global__ void combine_kernel(float* __restrict__ out) {
    int s = blockIdx.x;
    int t = threadIdx.x;
    float g1 = g_g1[s], g2 = g_g2[s];
    int i1 = g_idx1[s], i2 = g_idx2[s];
    int l1 = g_loc1[s], l2 = g_loc2[s];
    bool k1 = (l1 < CAP), k2 = (l2 < CAP);

    float4 r = make_float4(0.f, 0.f, 0.f, 0.f);
    if (k1) {
        const float4* p = (const float4*)(g_eo + ((size_t)i1 * CAP + l1) * MDIM);
        float4 v = p[t];
        r.x += g1 * v.x; r.y += g1 * v.y; r.z += g1 * v.z; r.w += g1 * v.w;
    }
    if (k2) {
        const float4* p = (const float4*)(g_eo + ((size_t)i2 * CAP + l2) * MDIM);
        float4 v = p[t];
        r.x += g2 * v.x; r.y += g2 * v.y; r.z += g2 * v.z; r.w += g2 * v.w;
    }
    ((float4*)(out + (size_t)s * MDIM))[t] = r;
}

// ======================= launch =============================================
extern "C" void kernel_launch(void* const* d_in, const int* in_sizes, int n_in,
                              void* d_out, int out_size) {
    const float* x  = (const float*)d_in[0];
    const float* wg = (const float*)d_in[1];
    const float* w1 = (const float*)d_in[2];
    const float* w2 = (const float*)d_in[3];
    float* out = (float*)d_out;
    float* laux_ptr = (out_size > SDIM * MDIM) ? (out + (size_t)SDIM * MDIM) : nullptr;

    // opt into >48KB dynamic smem (idempotent; called every launch, no guards)
    cudaFuncSetAttribute(mma_gemm_kernel<MDIM, FDIM, true>,
                         cudaFuncAttributeMaxDynamicSharedMemorySize, GEMM_DSMEM);
    cudaFuncSetAttribute(mma_gemm_kernel<FDIM, MDIM, false>,
                         cudaFuncAttributeMaxDynamicSharedMemorySize, GEMM_DSMEM);

    gate_kernel<<<SDIM / 8, 256>>>(x, wg);
    scan_kernel<<<1, 256>>>(laux_ptr);
    init_slot_kernel<<<(EDIM * CAP + 255) / 256, 256>>>();
    finalize_kernel<<<SDIM / 256, 256>>>();
    convert_x_kernel<<<EDIM * CAP, 256>>>(x);
    // w1 [e][M][F] -> g_w1t [e][F][M]
    transpose_split_kernel<1><<<dim3(FDIM / 32, MDIM / 32, EDIM), dim3(32, 8)>>>(
        w1, MDIM, FDIM);
    // w2 [e][F][M] -> g_w2t [e][M][F]
    transpose_split_kernel<2><<<dim3(MDIM / 32, FDIM / 32, EDIM), dim3(32, 8)>>>(
        w2, FDIM, MDIM);
    // GEMM1: [CAP x M] @ w1t^T -> relu -> g_h (bf16 hi/lo)
    mma_gemm_kernel<MDIM, FDIM, true>
        <<<dim3(FDIM / BN, CAP / BM, EDIM), 256, GEMM_DSMEM>>>();
    // GEMM2: [CAP x F] @ w2t^T -> g_eo (fp32)
    mma_gemm_kernel<FDIM, MDIM, false>
        <<<dim3(MDIM / BN, CAP / BM, EDIM), 256, GEMM_DSMEM>>>();
    combine_kernel<<<SDIM, 256>>>(out);
}

// round 13
// speedup vs baseline: 2.2582x; 1.0591x over previous
#include <cuda_runtime.h>
#include <cuda_bf16.h>
#include <math.h>
#include <stdint.h>

// Problem constants (fixed shapes for MOELayer_53772990545994)
#define SDIM 4096      // S = B*T tokens
#define MDIM 1024      // model dim
#define EDIM 8         // experts
#define FDIM 4096      // ffn dim
#define CAP  1024      // capacity = 2*S/E

// ======================= helpers ===========================================
__device__ __forceinline__ uint32_t smem_u32(const void* p) {
    uint32_t a;
    asm("{ .reg .u64 t; cvta.to.shared.u64 t, %1; cvt.u32.u64 %0, t; }"
        : "=r"(a) : "l"(p));
    return a;
}
__device__ __forceinline__ void cp_async16(uint32_t saddr, const void* g) {
    asm volatile("cp.async.cg.shared.global [%0], [%1], 16;"
                 :: "r"(saddr), "l"(g) : "memory");
}
#define CP_COMMIT() asm volatile("cp.async.commit_group;" ::: "memory")
#define CP_WAIT1()  asm volatile("cp.async.wait_group 1;" ::: "memory")

__device__ __forceinline__ void ldsm_x4(uint32_t* r, uint32_t a) {
    asm volatile("ldmatrix.sync.aligned.m8n8.x4.shared.b16 {%0,%1,%2,%3}, [%4];"
                 : "=r"(r[0]), "=r"(r[1]), "=r"(r[2]), "=r"(r[3]) : "r"(a));
}
__device__ __forceinline__ void mma16816(float* c, const uint32_t* a, const uint32_t* b) {
    asm volatile("mma.sync.aligned.m16n8k16.row.col.f32.bf16.bf16.f32 "
                 "{%0,%1,%2,%3}, {%4,%5,%6,%7}, {%8,%9}, {%0,%1,%2,%3};"
                 : "+f"(c[0]), "+f"(c[1]), "+f"(c[2]), "+f"(c[3])
                 : "r"(a[0]), "r"(a[1]), "r"(a[2]), "r"(a[3]),
                   "r"(b[0]), "r"(b[1]));
}

// ======================= scratch (device globals) ===========================
// NOTE: only referenced from device code (host sees shadow addresses).
__device__ float g_gates[SDIM * EDIM];
__device__ int   g_idx1[SDIM], g_idx2[SDIM];
__device__ int   g_loc1[SDIM], g_loc2[SDIM];
__device__ float g_g1raw[SDIM], g_g2raw[SDIM];
__device__ float g_g1[SDIM], g_g2[SDIM];
__device__ int   g_slot[EDIM * CAP];
__device__ __nv_bfloat16 g_xa_hi[(size_t)EDIM * CAP * MDIM];
__device__ __nv_bfloat16 g_xa_lo[(size_t)EDIM * CAP * MDIM];
__device__ __nv_bfloat16 g_w1t_hi[(size_t)EDIM * FDIM * MDIM];  // [e][f][m]
__device__ __nv_bfloat16 g_w1t_lo[(size_t)EDIM * FDIM * MDIM];
__device__ __nv_bfloat16 g_w2t_hi[(size_t)EDIM * MDIM * FDIM];  // [e][m][f]
__device__ __nv_bfloat16 g_w2t_lo[(size_t)EDIM * MDIM * FDIM];
__device__ __nv_bfloat16 g_h_hi[(size_t)EDIM * CAP * FDIM];
__device__ __nv_bfloat16 g_h_lo[(size_t)EDIM * CAP * FDIM];
__device__ float g_eo[(size_t)EDIM * CAP * MDIM];

// ======================= 1) gating ==========================================
__global__ void gate_kernel(const float* __restrict__ x,
                            const float* __restrict__ wg) {
    int warp = (blockIdx.x * blockDim.x + threadIdx.x) >> 5;
    int lane = threadIdx.x & 31;
    if (warp >= SDIM) return;
    const float* xr = x + (size_t)warp * MDIM;

    float acc[EDIM];
#pragma unroll
    for (int e = 0; e < EDIM; e++) acc[e] = 0.f;
    for (int m = lane; m < MDIM; m += 32) {
        float xv = xr[m];
        const float4* w4 = (const float4*)(wg + (size_t)m * EDIM);
        float4 a = w4[0], b = w4[1];
        acc[0] += xv * a.x; acc[1] += xv * a.y;
        acc[2] += xv * a.z; acc[3] += xv * a.w;
        acc[4] += xv * b.x; acc[5] += xv * b.y;
        acc[6] += xv * b.z; acc[7] += xv * b.w;
    }
#pragma unroll
    for (int o = 16; o > 0; o >>= 1)
#pragma unroll
        for (int e = 0; e < EDIM; e++)
            acc[e] += __shfl_xor_sync(0xffffffffu, acc[e], o);

    if (lane == 0) {
        float mx = acc[0];
#pragma unroll
        for (int e = 1; e < EDIM; e++) mx = fmaxf(mx, acc[e]);
        float p[EDIM], sum = 0.f;
#pragma unroll
        for (int e = 0; e < EDIM; e++) { p[e] = expf(acc[e] - mx); sum += p[e]; }
        float inv = 1.f / sum;
#pragma unroll
        for (int e = 0; e < EDIM; e++) {
            p[e] *= inv;
            g_gates[warp * EDIM + e] = p[e];
        }
        int i1 = 0;
#pragma unroll
        for (int e = 1; e < EDIM; e++) if (acc[e] > acc[i1]) i1 = e;
        int i2 = (i1 == 0) ? 1 : 0;
#pragma unroll
        for (int e = 0; e < EDIM; e++)
            if (e != i1 && acc[e] > acc[i2]) i2 = e;
        g_idx1[warp] = i1; g_idx2[warp] = i2;
        g_g1raw[warp] = p[i1]; g_g2raw[warp] = p[i2];
    }
}

// ======================= 2) scan (single block) =============================
__global__ void scan_kernel(float* laux_ptr) {
    __shared__ int   sCnt1[EDIM];
    __shared__ float sGsum[EDIM];
    int w    = threadIdx.x >> 5;
    int lane = threadIdx.x & 31;
    unsigned ltmask = (1u << lane) - 1u;

    int base = 0;
    for (int s0 = 0; s0 < SDIM; s0 += 32) {
        int s = s0 + lane;
        bool m = (g_idx1[s] == w);
        unsigned bal = __ballot_sync(0xffffffffu, m);
        if (m) g_loc1[s] = base + __popc(bal & ltmask);
        base += __popc(bal);
    }
    if (lane == 0) sCnt1[w] = base;
    __syncthreads();

    int base2 = sCnt1[w];
    for (int s0 = 0; s0 < SDIM; s0 += 32) {
        int s = s0 + lane;
        bool m = (g_idx2[s] == w);
        unsigned bal = __ballot_sync(0xffffffffu, m);
        if (m) g_loc2[s] = base2 + __popc(bal & ltmask);
        base2 += __popc(bal);
    }

    float acc = 0.f;
    for (int s = lane; s < SDIM; s += 32) acc += g_gates[s * EDIM + w];
#pragma unroll
    for (int o = 16; o > 0; o >>= 1) acc += __shfl_xor_sync(0xffffffffu, acc, o);
    if (lane == 0) sGsum[w] = acc;
    __syncthreads();

    if (threadIdx.x == 0 && laux_ptr != nullptr) {
        float l = 0.f;
#pragma unroll
        for (int e = 0; e < EDIM; e++) l += sGsum[e] * (float)sCnt1[e];
        *laux_ptr = l * (float)EDIM / ((float)SDIM * (float)SDIM);
    }
}

// ======================= 3) slot init + finalize ============================
__global__ void init_slot_kernel() {
    int i = blockIdx.x * blockDim.x + threadIdx.x;
    if (i < EDIM * CAP) g_slot[i] = -1;
}

__global__ void finalize_kernel() {
    int s = blockIdx.x * blockDim.x + threadIdx.x;
    if (s >= SDIM) return;
    int l1 = g_loc1[s], l2 = g_loc2[s];
    int i1 = g_idx1[s], i2 = g_idx2[s];
    bool k1 = (l1 < CAP), k2 = (l2 < CAP);
    float g1s = k1 ? g_g1raw[s] : 0.f;
    float g2s = k2 ? g_g2raw[s] : 0.f;
    float den = g1s + g2s;
    if (den < 1e-9f) den = 1e-9f;
    g_g1[s] = g1s / den;
    g_g2[s] = g2s / den;
    if (k1) g_slot[i1 * CAP + l1] = s;
    if (k2) g_slot[i2 * CAP + l2] = s;
}

// ======================= 4) convert + gather x into bf16 hi/lo ==============
__global__ void convert_x_kernel(const float* __restrict__ x) {
    int slot = blockIdx.x;        // 0..8191
    int t = threadIdx.x;          // 256 threads * 4 elems
    int tok = g_slot[slot];
    float4 v = make_float4(0.f, 0.f, 0.f, 0.f);
    if (tok >= 0) v = ((const float4*)(x + (size_t)tok * MDIM))[t];
    __nv_bfloat16 h[4], l[4];
    float f[4] = {v.x, v.y, v.z, v.w};
#pragma unroll
    for (int i = 0; i < 4; i++) {
        h[i] = __float2bfloat16(f[i]);
        l[i] = __float2bfloat16(f[i] - __bfloat162float(h[i]));
    }
    size_t off = (size_t)slot * MDIM + t * 4;
    *(uint2*)&g_xa_hi[off] = *(uint2*)h;
    *(uint2*)&g_xa_lo[off] = *(uint2*)l;
}

// ======================= 5) weight transpose + split ========================
// in: [E][R][Cc] fp32 -> g_wXt hi/lo: [E][Cc][R] bf16.  WHICH: 1 -> w1t, 2 -> w2t.
template<int WHICH>
__global__ void transpose_split_kernel(const float* __restrict__ in,
                                       int R, int Cc) {
    __nv_bfloat16* oh = (WHICH == 1) ? g_w1t_hi : g_w2t_hi;
    __nv_bfloat16* ol = (WHICH == 1) ? g_w1t_lo : g_w2t_lo;
    __shared__ float t[32][33];
    int e = blockIdx.z;
    int c0 = blockIdx.x * 32, r0 = blockIdx.y * 32;
    const float* ip = in + (size_t)e * R * Cc;
    for (int i = threadIdx.y; i < 32; i += 8)
        t[i][threadIdx.x] = ip[(size_t)(r0 + i) * Cc + c0 + threadIdx.x];
    __syncthreads();
    size_t ob = (size_t)e * R * Cc;
    for (int i = threadIdx.y; i < 32; i += 8) {
        float v = t[threadIdx.x][i];
        __nv_bfloat16 h = __float2bfloat16(v);
        float lo = v - __bfloat162float(h);
        size_t o = ob + (size_t)(c0 + i) * R + r0 + threadIdx.x;
        oh[o] = h;
        ol[o] = __float2bfloat16(lo);
    }
}

// ======================= 6) bf16 HMMA GEMM (mma.sync) =======================
// C[128x128] per CTA = sum over 3 segments of A[128xK] @ B[128xK]^T:
//   seg0: Ahi*Bhi, seg1: Alo*Bhi, seg2: Ahi*Blo   (3-term fp32-split)
// 8 warps (2x4), warp tile 64x32, m16n8k16 HMMA, ldmatrix.x4 fragments.
// BK=64 chunks, 3-stage cp.async pipeline, one __syncthreads per chunk.
// 110592 B dyn smem + <=128 regs -> 2 CTAs/SM (16 warps, 4/SMSP).
#define BM 128
#define BN 128
#define BK 64
#define NSTAGE 3
#define SROWB 144
#define A_BYTES (128 * SROWB)            // 18432
#define B_BYTES (128 * SROWB)            // 18432
#define STAGE_BYTES (A_BYTES + B_BYTES)  // 36864
#define B_SOFF A_BYTES
#define GEMM_DSMEM (NSTAGE * STAGE_BYTES) // 110592

template<int KDIM, int NTOT, bool FFN1>
__global__ __launch_bounds__(256, 2) void mma_gemm_kernel() {
    extern __shared__ char smbuf[];
    const int tid  = threadIdx.x;
    const int wid  = tid >> 5;
    const int lane = tid & 31;
    const int e    = blockIdx.z;
    const int row0 = blockIdx.y * BM;
    const int col0 = blockIdx.x * BN;
    const int KI   = KDIM / BK;       // chunks per segment
    const int NK   = 3 * KI;

    const int wm = (wid >> 2) * 64;   // warp row offset (2 groups of 64)
    const int wn = (wid & 3) * 32;    // warp col offset (4 groups of 32)
    const int lq = lane >> 2;         // 0..7
    const int lr = lane & 3;          // 0..3

    uint32_t sbase = smem_u32(smbuf);

    // device-side symbol resolution
    const __nv_bfloat16* Ahi = FFN1 ? g_xa_hi  : g_h_hi;
    const __nv_bfloat16* Alo = FFN1 ? g_xa_lo  : g_h_lo;
    const __nv_bfloat16* Bhi = FFN1 ? g_w1t_hi : g_w2t_hi;
    const __nv_bfloat16* Blo = FFN1 ? g_w1t_lo : g_w2t_lo;

    const __nv_bfloat16* Ah = Ahi + ((size_t)e * CAP  + row0) * KDIM;
    const __nv_bfloat16* Al = Alo + ((size_t)e * CAP  + row0) * KDIM;
    const __nv_bfloat16* Bh = Bhi + ((size_t)e * NTOT + col0) * KDIM;
    const __nv_bfloat16* Bl = Blo + ((size_t)e * NTOT + col0) * KDIM;

    // chunk p -> (segment, k-offset); A tile 128x64, B tile 128x64
    auto prefetch = [&](int p) {
        int seg = p / KI;
        int kk  = (p - seg * KI) * BK;
        const __nv_bfloat16* Ap = (seg == 1) ? Al : Ah;
        const __nv_bfloat16* Bp = (seg == 2) ? Bl : Bh;
        uint32_t sb = sbase + (uint32_t)(p % NSTAGE) * STAGE_BYTES;
#pragma unroll
        for (int c = tid; c < 2048; c += 256) {
            int r = (c >> 3) & 127;
            int q = c & 7;
            if (c < 1024)                   // A: 128 rows x 8 16B-chunks
                cp_async16(sb + r * SROWB + q * 16,
                           Ap + (size_t)r * KDIM + kk + q * 8);
            else                            // B: 128 rows x 8 16B-chunks
                cp_async16(sb + B_SOFF + r * SROWB + q * 16,
                           Bp + (size_t)r * KDIM + kk + q * 8);
        }
    };

    float acc[4][4][4];
#pragma unroll
    for (int i = 0; i < 4; i++)
#pragma unroll
        for (int j = 0; j < 4; j++)
#pragma unroll
            for (int k = 0; k < 4; k++) acc[i][j][k] = 0.f;

    prefetch(0); CP_COMMIT();
    prefetch(1); CP_COMMIT();

    // per-thread intra-fragment offsets (constant over loop)
    const int a_row  = lane & 15;
    const int a_half = (lane >> 4) << 4;
    const int b_grp  = lane >> 3;           // 0..3
    const int b_row  = (b_grp >> 1) * 8 + (lane & 7);
    const int b_half = (b_grp & 1) << 4;

    for (int i = 0; i < NK; i++) {
        CP_WAIT1();             // chunk i resident (i+1 may be in flight)
        __syncthreads();        // all warps done reading stage (i-1)%3
        if (i + 2 < NK) prefetch(i + 2);
        CP_COMMIT();

        uint32_t sb = sbase + (uint32_t)(i % NSTAGE) * STAGE_BYTES;
#pragma unroll
        for (int ks = 0; ks < 4; ks++) {
            uint32_t a[4][4], bf[2][4];
#pragma unroll
            for (int mt = 0; mt < 4; mt++) {
                uint32_t addr = sb + (uint32_t)(wm + mt * 16 + a_row) * SROWB
                              + ks * 32 + a_half;
                ldsm_x4(a[mt], addr);
            }
#pragma unroll
            for (int np = 0; np < 2; np++) {   // covers nt=2np, 2np+1
                uint32_t addr = sb + B_SOFF
                              + (uint32_t)(wn + np * 16 + b_row) * SROWB
                              + ks * 32 + b_half;
                ldsm_x4(bf[np], addr);
            }
#pragma unroll
            for (int mt = 0; mt < 4; mt++)
#pragma unroll
                for (int nt = 0; nt < 4; nt++)
                    mma16816(acc[mt][nt], a[mt], &bf[nt >> 1][(nt & 1) * 2]);
        }
    }

    // epilogue: c0/c1 at (row=lq, col=lr*2), c2/c3 at row lq+8
#pragma unroll
    for (int mt = 0; mt < 4; mt++) {
#pragma unroll
        for (int half = 0; half < 2; half++) {
            int grow = row0 + wm + mt * 16 + lq + half * 8;
            size_t rowg = (size_t)e * CAP + grow;
#pragma unroll
            for (int nt = 0; nt < 4; nt++) {
                float v0 = acc[mt][nt][half * 2 + 0];
                float v1 = acc[mt][nt][half * 2 + 1];
                int gcol = col0 + wn + nt * 8 + lr * 2;
                if (FFN1) {
                    v0 = fmaxf(v0, 0.f); v1 = fmaxf(v1, 0.f);
                    __nv_bfloat16 h0 = __float2bfloat16(v0);
                    __nv_bfloat16 h1 = __float2bfloat16(v1);
                    __nv_bfloat16 l0 = __float2bfloat16(v0 - __bfloat162float(h0));
                    __nv_bfloat16 l1 = __float2bfloat16(v1 - __bfloat162float(h1));
                    __nv_bfloat162 hv; hv.x = h0; hv.y = h1;
                    __nv_bfloat162 lv; lv.x = l0; lv.y = l1;
                    *(__nv_bfloat162*)&g_h_hi[rowg * FDIM + gcol] = hv;
                    *(__nv_bfloat162*)&g_h_lo[rowg * FDIM + gcol] = lv;
                } else {
                    float2 o; o.x = v0; o.y = v1;
                    *(float2*)&g_eo[rowg * MDIM + gcol] = o;
                }
            }
        }
    }
}

// ======================= 7) combine =========================================
__global__ void combine_kernel(float* __restrict__ out) {
    int s = blockIdx.x;
    int t = threadIdx.x;
    float g1 = g_g1[s], g2 = g_g2[s];
    int i1 = g_idx1[s], i2 = g_idx2[s];
    int l1 = g_loc1[s], l2 = g_loc2[s];
    bool k1 = (l1 < CAP), k2 = (l2 < CAP);

    float4 r = make_float4(0.f, 0.f, 0.f, 0.f);
    if (k1) {
        const float4* p = (const float4*)(g_eo + ((size_t)i1 * CAP + l1) * MDIM);
        float4 v = p[t];
        r.x += g1 * v.x; r.y += g1 * v.y; r.z += g1 * v.z; r.w += g1 * v.w;
    }
    if (k2) {
        const float4* p = (const float4*)(g_eo + ((size_t)i2 * CAP + l2) * MDIM);
        float4 v = p[t];
        r.x += g2 * v.x; r.y += g2 * v.y; r.z += g2 * v.z; r.w += g2 * v.w;
    }
    ((float4*)(out + (size_t)s * MDIM))[t] = r;
}

// ======================= launch =============================================
extern "C" void kernel_launch(void* const* d_in, const int* in_sizes, int n_in,
                              void* d_out, int out_size) {
    const float* x  = (const float*)d_in[0];
    const float* wg = (const float*)d_in[1];
    const float* w1 = (const float*)d_in[2];
    const float* w2 = (const float*)d_in[3];
    float* out = (float*)d_out;
    float* laux_ptr = (out_size > SDIM * MDIM) ? (out + (size_t)SDIM * MDIM) : nullptr;

    // opt into >48KB dynamic smem (idempotent; called every launch, no guards)
    cudaFuncSetAttribute(mma_gemm_kernel<MDIM, FDIM, true>,
                         cudaFuncAttributeMaxDynamicSharedMemorySize, GEMM_DSMEM);
    cudaFuncSetAttribute(mma_gemm_kernel<FDIM, MDIM, false>,
                         cudaFuncAttributeMaxDynamicSharedMemorySize, GEMM_DSMEM);

    gate_kernel<<<SDIM / 8, 256>>>(x, wg);
    scan_kernel<<<1, 256>>>(laux_ptr);
    init_slot_kernel<<<(EDIM * CAP + 255) / 256, 256>>>();
    finalize_kernel<<<SDIM / 256, 256>>>();
    convert_x_kernel<<<EDIM * CAP, 256>>>(x);
    // w1 [e][M][F] -> g_w1t [e][F][M]
    transpose_split_kernel<1><<<dim3(FDIM / 32, MDIM / 32, EDIM), dim3(32, 8)>>>(
        w1, MDIM, FDIM);
    // w2 [e][F][M] -> g_w2t [e][M][F]
    transpose_split_kernel<2><<<dim3(MDIM / 32, FDIM / 32, EDIM), dim3(32, 8)>>>(
        w2, FDIM, MDIM);
    // GEMM1: [CAP x M] @ w1t^T -> relu -> g_h (bf16 hi/lo)
    mma_gemm_kernel<MDIM, FDIM, true>
        <<<dim3(FDIM / BN, CAP / BM, EDIM), 256, GEMM_DSMEM>>>();
    // GEMM2: [CAP x F] @ w2t^T -> g_eo (fp32)
    mma_gemm_kernel<FDIM, MDIM, false>
        <<<dim3(MDIM / BN, CAP / BM, EDIM), 256, GEMM_DSMEM>>>();
    combine_kernel<<<SDIM, 256>>>(out);
}

// round 15
// speedup vs baseline: 3.3383x; 1.4783x over previous
#include <cuda_runtime.h>
#include <cuda_fp16.h>
#include <math.h>
#include <stdint.h>

// Problem constants (fixed shapes for MOELayer_53772990545994)
#define SDIM 4096      // S = B*T tokens
#define MDIM 1024      // model dim
#define EDIM 8         // experts
#define FDIM 4096      // ffn dim
#define CAP  1024      // capacity = 2*S/E

// ======================= helpers ===========================================
__device__ __forceinline__ uint32_t smem_u32(const void* p) {
    uint32_t a;
    asm("{ .reg .u64 t; cvta.to.shared.u64 t, %1; cvt.u32.u64 %0, t; }"
        : "=r"(a) : "l"(p));
    return a;
}
__device__ __forceinline__ void cp_async16(uint32_t saddr, const void* g) {
    asm volatile("cp.async.cg.shared.global [%0], [%1], 16;"
                 :: "r"(saddr), "l"(g) : "memory");
}
#define CP_COMMIT() asm volatile("cp.async.commit_group;" ::: "memory")
#define CP_WAIT1()  asm volatile("cp.async.wait_group 1;" ::: "memory")
#define CP_WAIT0()  asm volatile("cp.async.wait_group 0;" ::: "memory")

__device__ __forceinline__ void ldsm_x4(uint32_t* r, uint32_t a) {
    asm volatile("ldmatrix.sync.aligned.m8n8.x4.shared.b16 {%0,%1,%2,%3}, [%4];"
                 : "=r"(r[0]), "=r"(r[1]), "=r"(r[2]), "=r"(r[3]) : "r"(a));
}
// fp16 inputs, fp32 accumulate
__device__ __forceinline__ void mma16816(float* c, const uint32_t* a, const uint32_t* b) {
    asm volatile("mma.sync.aligned.m16n8k16.row.col.f32.f16.f16.f32 "
                 "{%0,%1,%2,%3}, {%4,%5,%6,%7}, {%8,%9}, {%0,%1,%2,%3};"
                 : "+f"(c[0]), "+f"(c[1]), "+f"(c[2]), "+f"(c[3])
                 : "r"(a[0]), "r"(a[1]), "r"(a[2]), "r"(a[3]),
                   "r"(b[0]), "r"(b[1]));
}

// ======================= scratch (device globals) ===========================
// NOTE: only referenced from device code (host sees shadow addresses).
__device__ float g_gates[SDIM * EDIM];
__device__ int   g_idx1[SDIM], g_idx2[SDIM];
__device__ int   g_loc1[SDIM], g_loc2[SDIM];
__device__ float g_g1raw[SDIM], g_g2raw[SDIM];
__device__ float g_g1[SDIM], g_g2[SDIM];
__device__ int   g_slot[EDIM * CAP];
// fp16 operand storage: A-side 2-way split (hi+lo), B-side single fp16
__device__ __half g_xa_hi[(size_t)EDIM * CAP * MDIM];
__device__ __half g_xa_lo[(size_t)EDIM * CAP * MDIM];
__device__ __half g_w1t[(size_t)EDIM * FDIM * MDIM];  // [e][f][m]
__device__ __half g_w2t[(size_t)EDIM * MDIM * FDIM];  // [e][m][f]
__device__ __half g_h_hi[(size_t)EDIM * CAP * FDIM];
__device__ __half g_h_lo[(size_t)EDIM * CAP * FDIM];
__device__ float g_eo[(size_t)EDIM * CAP * MDIM];

// ======================= 1) gating ==========================================
__global__ void gate_kernel(const float* __restrict__ x,
                            const float* __restrict__ wg) {
    int warp = (blockIdx.x * blockDim.x + threadIdx.x) >> 5;
    int lane = threadIdx.x & 31;
    if (warp >= SDIM) return;
    const float* xr = x + (size_t)warp * MDIM;

    float acc[EDIM];
#pragma unroll
    for (int e = 0; e < EDIM; e++) acc[e] = 0.f;
    for (int m = lane; m < MDIM; m += 32) {
        float xv = xr[m];
        const float4* w4 = (const float4*)(wg + (size_t)m * EDIM);
        float4 a = w4[0], b = w4[1];
        acc[0] += xv * a.x; acc[1] += xv * a.y;
        acc[2] += xv * a.z; acc[3] += xv * a.w;
        acc[4] += xv * b.x; acc[5] += xv * b.y;
        acc[6] += xv * b.z; acc[7] += xv * b.w;
    }
#pragma unroll
    for (int o = 16; o > 0; o >>= 1)
#pragma unroll
        for (int e = 0; e < EDIM; e++)
            acc[e] += __shfl_xor_sync(0xffffffffu, acc[e], o);

    if (lane == 0) {
        float mx = acc[0];
#pragma unroll
        for (int e = 1; e < EDIM; e++) mx = fmaxf(mx, acc[e]);
        float p[EDIM], sum = 0.f;
#pragma unroll
        for (int e = 0; e < EDIM; e++) { p[e] = expf(acc[e] - mx); sum += p[e]; }
        float inv = 1.f / sum;
#pragma unroll
        for (int e = 0; e < EDIM; e++) {
            p[e] *= inv;
            g_gates[warp * EDIM + e] = p[e];
        }
        int i1 = 0;
#pragma unroll
        for (int e = 1; e < EDIM; e++) if (acc[e] > acc[i1]) i1 = e;
        int i2 = (i1 == 0) ? 1 : 0;
#pragma unroll
        for (int e = 0; e < EDIM; e++)
            if (e != i1 && acc[e] > acc[i2]) i2 = e;
        g_idx1[warp] = i1; g_idx2[warp] = i2;
        g_g1raw[warp] = p[i1]; g_g2raw[warp] = p[i2];
    }
}

// ======================= 2) scan (single block) =============================
__global__ void scan_kernel(float* laux_ptr) {
    __shared__ int   sCnt1[EDIM];
    __shared__ float sGsum[EDIM];
    int w    = threadIdx.x >> 5;
    int lane = threadIdx.x & 31;
    unsigned ltmask = (1u << lane) - 1u;

    int base = 0;
    for (int s0 = 0; s0 < SDIM; s0 += 32) {
        int s = s0 + lane;
        bool m = (g_idx1[s] == w);
        unsigned bal = __ballot_sync(0xffffffffu, m);
        if (m) g_loc1[s] = base + __popc(bal & ltmask);
        base += __popc(bal);
    }
    if (lane == 0) sCnt1[w] = base;
    __syncthreads();

    int base2 = sCnt1[w];
    for (int s0 = 0; s0 < SDIM; s0 += 32) {
        int s = s0 + lane;
        bool m = (g_idx2[s] == w);
        unsigned bal = __ballot_sync(0xffffffffu, m);
        if (m) g_loc2[s] = base2 + __popc(bal & ltmask);
        base2 += __popc(bal);
    }

    float acc = 0.f;
    for (int s = lane; s < SDIM; s += 32) acc += g_gates[s * EDIM + w];
#pragma unroll
    for (int o = 16; o > 0; o >>= 1) acc += __shfl_xor_sync(0xffffffffu, acc, o);
    if (lane == 0) sGsum[w] = acc;
    __syncthreads();

    if (threadIdx.x == 0 && laux_ptr != nullptr) {
        float l = 0.f;
#pragma unroll
        for (int e = 0; e < EDIM; e++) l += sGsum[e] * (float)sCnt1[e];
        *laux_ptr = l * (float)EDIM / ((float)SDIM * (float)SDIM);
    }
}

// ======================= 3) slot init + finalize ============================
__global__ void init_slot_kernel() {
    int i = blockIdx.x * blockDim.x + threadIdx.x;
    if (i < EDIM * CAP) g_slot[i] = -1;
}

__global__ void finalize_kernel() {
    int s = blockIdx.x * blockDim.x + threadIdx.x;
    if (s >= SDIM) return;
    int l1 = g_loc1[s], l2 = g_loc2[s];
    int i1 = g_idx1[s], i2 = g_idx2[s];
    bool k1 = (l1 < CAP), k2 = (l2 < CAP);
    float g1s = k1 ? g_g1raw[s] : 0.f;
    float g2s = k2 ? g_g2raw[s] : 0.f;
    float den = g1s + g2s;
    if (den < 1e-9f) den = 1e-9f;
    g_g1[s] = g1s / den;
    g_g2[s] = g2s / den;
    if (k1) g_slot[i1 * CAP + l1] = s;
    if (k2) g_slot[i2 * CAP + l2] = s;
}

// ======================= 4) convert + gather x into fp16 hi/lo ==============
__global__ void convert_x_kernel(const float* __restrict__ x) {
    int slot = blockIdx.x;        // 0..8191
    int t = threadIdx.x;          // 256 threads * 4 elems
    int tok = g_slot[slot];
    float4 v = make_float4(0.f, 0.f, 0.f, 0.f);
    if (tok >= 0) v = ((const float4*)(x + (size_t)tok * MDIM))[t];
    __half h[4], l[4];
    float f[4] = {v.x, v.y, v.z, v.w};
#pragma unroll
    for (int i = 0; i < 4; i++) {
        h[i] = __float2half_rn(f[i]);
        l[i] = __float2half_rn(f[i] - __half2float(h[i]));
    }
    size_t off = (size_t)slot * MDIM + t * 4;
    *(uint2*)&g_xa_hi[off] = *(uint2*)h;
    *(uint2*)&g_xa_lo[off] = *(uint2*)l;
}

// ======================= 5) weight transpose (single fp16) ==================
// in: [E][R][Cc] fp32 -> g_wXt: [E][Cc][R] fp16.  WHICH: 1 -> w1t, 2 -> w2t.
template<int WHICH>
__global__ void transpose_split_kernel(const float* __restrict__ in,
                                       int R, int Cc) {
    __half* oh = (WHICH == 1) ? g_w1t : g_w2t;
    __shared__ float t[32][33];
    int e = blockIdx.z;
    int c0 = blockIdx.x * 32, r0 = blockIdx.y * 32;
    const float* ip = in + (size_t)e * R * Cc;
    for (int i = threadIdx.y; i < 32; i += 8)
        t[i][threadIdx.x] = ip[(size_t)(r0 + i) * Cc + c0 + threadIdx.x];
    __syncthreads();
    size_t ob = (size_t)e * R * Cc;
    for (int i = threadIdx.y; i < 32; i += 8) {
        float v = t[threadIdx.x][i];
        size_t o = ob + (size_t)(c0 + i) * R + r0 + threadIdx.x;
        oh[o] = __float2half_rn(v);
    }
}

// ======================= 6) fp16 HMMA GEMM (mma.sync) =======================
// C[128x128] per CTA = (Ahi + Alo)[128xK] @ B[128xK]^T  (2-term fp16 split;
// B tile shared by both passes -> loaded once per chunk).
// 8 warps (2x4), warp tile 64x32, m16n8k16 HMMA, ldmatrix.x4 fragments.
// BK=64 chunks; per-stage smem = {Ahi, Alo, B} tiles; 2-stage cp.async,
// 110592 B dyn smem + <=128 regs -> 2 CTAs/SM (16 warps, 4/SMSP).
#define BM 128
#define BN 128
#define BK 64
#define NSTAGE 2
#define SROWB 144
#define TILE_BYTES_ (128 * SROWB)             // 18432 per tile
#define ALO_SOFF TILE_BYTES_
#define B_SOFF   (2 * TILE_BYTES_)
#define STAGE_BYTES (3 * TILE_BYTES_)         // 55296
#define GEMM_DSMEM (NSTAGE * STAGE_BYTES)     // 110592

template<int KDIM, int NTOT, bool FFN1>
__global__ __launch_bounds__(256, 2) void mma_gemm_kernel() {
    extern __shared__ char smbuf[];
    const int tid  = threadIdx.x;
    const int wid  = tid >> 5;
    const int lane = tid & 31;
    const int e    = blockIdx.z;
    const int row0 = blockIdx.y * BM;
    const int col0 = blockIdx.x * BN;
    const int KI   = KDIM / BK;       // chunks

    const int wm = (wid >> 2) * 64;   // warp row offset (2 groups of 64)
    const int wn = (wid & 3) * 32;    // warp col offset (4 groups of 32)
    const int lq = lane >> 2;         // 0..7
    const int lr = lane & 3;          // 0..3

    uint32_t sbase = smem_u32(smbuf);

    // device-side symbol resolution
    const __half* Ahi = FFN1 ? g_xa_hi : g_h_hi;
    const __half* Alo = FFN1 ? g_xa_lo : g_h_lo;
    const __half* Bp  = FFN1 ? g_w1t   : g_w2t;

    const __half* Ah = Ahi + ((size_t)e * CAP  + row0) * KDIM;
    const __half* Al = Alo + ((size_t)e * CAP  + row0) * KDIM;
    const __half* Bb = Bp  + ((size_t)e * NTOT + col0) * KDIM;

    // chunk p: load Ahi, Alo, B tiles (128x64 fp16 each)
    auto prefetch = [&](int p) {
        int kk = p * BK;
        uint32_t sb = sbase + (uint32_t)(p & 1) * STAGE_BYTES;
#pragma unroll
        for (int c = tid; c < 3072; c += 256) {
            int r = (c >> 3) & 127;
            int q = c & 7;
            uint32_t so = (uint32_t)(r * SROWB + q * 16);
            size_t go = (size_t)r * KDIM + kk + q * 8;
            if (c < 1024)      cp_async16(sb + so,            Ah + go);
            else if (c < 2048) cp_async16(sb + ALO_SOFF + so, Al + go);
            else               cp_async16(sb + B_SOFF + so,   Bb + go);
        }
    };

    float acc[4][4][4];
#pragma unroll
    for (int i = 0; i < 4; i++)
#pragma unroll
        for (int j = 0; j < 4; j++)
#pragma unroll
            for (int k = 0; k < 4; k++) acc[i][j][k] = 0.f;

    prefetch(0); CP_COMMIT();

    // per-thread intra-fragment offsets
    const int a_row  = lane & 15;
    const int a_half = (lane >> 4) << 4;
    const int b_grp  = lane >> 3;           // 0..3
    const int b_row  = (b_grp >> 1) * 8 + (lane & 7);
    const int b_half = (b_grp & 1) << 4;

    for (int i = 0; i < KI; i++) {
        if (i + 1 < KI) {
            prefetch(i + 1); CP_COMMIT();
            CP_WAIT1();         // chunk i resident
        } else {
            CP_WAIT0();         // last chunk resident (exact tail wait)
        }
        __syncthreads();

        uint32_t sb = sbase + (uint32_t)(i & 1) * STAGE_BYTES;
#pragma unroll
        for (int ks = 0; ks < 4; ks++) {
            uint32_t a[4][4], bf[2][4];
#pragma unroll
            for (int np = 0; np < 2; np++) {
                uint32_t addr = sb + B_SOFF
                              + (uint32_t)(wn + np * 16 + b_row) * SROWB
                              + ks * 32 + b_half;
                ldsm_x4(bf[np], addr);
            }
            // pass 1: A_hi
#pragma unroll
            for (int mt = 0; mt < 4; mt++) {
                uint32_t addr = sb + (uint32_t)(wm + mt * 16 + a_row) * SROWB
                              + ks * 32 + a_half;
                ldsm_x4(a[mt], addr);
            }
#pragma unroll
            for (int mt = 0; mt < 4; mt++)
#pragma unroll
                for (int nt = 0; nt < 4; nt++)
                    mma16816(acc[mt][nt], a[mt], &bf[nt >> 1][(nt & 1) * 2]);
            // pass 2: A_lo (same B fragments)
#pragma unroll
            for (int mt = 0; mt < 4; mt++) {
                uint32_t addr = sb + ALO_SOFF
                              + (uint32_t)(wm + mt * 16 + a_row) * SROWB
                              + ks * 32 + a_half;
                ldsm_x4(a[mt], addr);
            }
#pragma unroll
            for (int mt = 0; mt < 4; mt++)
#pragma unroll
                for (int nt = 0; nt < 4; nt++)
                    mma16816(acc[mt][nt], a[mt], &bf[nt >> 1][(nt & 1) * 2]);
        }
        __syncthreads();        // stage may be overwritten next iter
    }

    // epilogue: c0/c1 at (row=lq, col=lr*2), c2/c3 at row lq+8
#pragma unroll
    for (int mt = 0; mt < 4; mt++) {
#pragma unroll
        for (int half = 0; half < 2; half++) {
            int grow = row0 + wm + mt * 16 + lq + half * 8;
            size_t rowg = (size_t)e * CAP + grow;
#pragma unroll
            for (int nt = 0; nt < 4; nt++) {
                float v0 = acc[mt][nt][half * 2 + 0];
                float v1 = acc[mt][nt][half * 2 + 1];
                int gcol = col0 + wn + nt * 8 + lr * 2;
                if (FFN1) {
                    v0 = fmaxf(v0, 0.f); v1 = fmaxf(v1, 0.f);
                    __half h0 = __float2half_rn(v0);
                    __half h1 = __float2half_rn(v1);
                    __half l0 = __float2half_rn(v0 - __half2float(h0));
                    __half l1 = __float2half_rn(v1 - __half2float(h1));
                    __half2 hv = __halves2half2(h0, h1);
                    __half2 lv = __halves2half2(l0, l1);
                    *(__half2*)&g_h_hi[rowg * FDIM + gcol] = hv;
                    *(__half2*)&g_h_lo[rowg * FDIM + gcol] = lv;
                } else {
                    float2 o; o.x = v0; o.y = v1;
                    *(float2*)&g_eo[rowg * MDIM + gcol] = o;
                }
            }
        }
    }
}

// ======================= 7) combine =========================================
__global__ void combine_kernel(float* __restrict__ out) {
    int s = blockIdx.x;
    int t = threadIdx.x;
    float g1 = g_g1[s], g2 = g_g2[s];
    int i1 = g_idx1[s], i2 = g_idx2[s];
    int l1 = g_loc1[s], l2 = g_loc2[s];
    bool k1 = (l1 < CAP), k2 = (l2 < CAP);

    float4 r = make_float4(0.f, 0.f, 0.f, 0.f);
    if (k1) {
        const float4* p = (const float4*)(g_eo + ((size_t)i1 * CAP + l1) * MDIM);
        float4 v = p[t];
        r.x += g1 * v.x; r.y += g1 * v.y; r.z += g1 * v.z; r.w += g1 * v.w;
    }
    if (k2) {
        const float4* p = (const float4*)(g_eo + ((size_t)i2 * CAP + l2) * MDIM);
        float4 v = p[t];
        r.x += g2 * v.x; r.y += g2 * v.y; r.z += g2 * v.z; r.w += g2 * v.w;
    }
    ((float4*)(out + (size_t)s * MDIM))[t] = r;
}

// ======================= launch =============================================
extern "C" void kernel_launch(void* const* d_in, const int* in_sizes, int n_in,
                              void* d_out, int out_size) {
    const float* x  = (const float*)d_in[0];
    const float* wg = (const float*)d_in[1];
    const float* w1 = (const float*)d_in[2];
    const float* w2 = (const float*)d_in[3];
    float* out = (float*)d_out;
    float* laux_ptr = (out_size > SDIM * MDIM) ? (out + (size_t)SDIM * MDIM) : nullptr;

    // opt into >48KB dynamic smem (idempotent; called every launch, no guards)
    cudaFuncSetAttribute(mma_gemm_kernel<MDIM, FDIM, true>,
                         cudaFuncAttributeMaxDynamicSharedMemorySize, GEMM_DSMEM);
    cudaFuncSetAttribute(mma_gemm_kernel<FDIM, MDIM, false>,
                         cudaFuncAttributeMaxDynamicSharedMemorySize, GEMM_DSMEM);

    gate_kernel<<<SDIM / 8, 256>>>(x, wg);
    scan_kernel<<<1, 256>>>(laux_ptr);
    init_slot_kernel<<<(EDIM * CAP + 255) / 256, 256>>>();
    finalize_kernel<<<SDIM / 256, 256>>>();
    convert_x_kernel<<<EDIM * CAP, 256>>>(x);
    // w1 [e][M][F] -> g_w1t [e][F][M] fp16
    transpose_split_kernel<1><<<dim3(FDIM / 32, MDIM / 32, EDIM), dim3(32, 8)>>>(
        w1, MDIM, FDIM);
    // w2 [e][F][M] -> g_w2t [e][M][F] fp16
    transpose_split_kernel<2><<<dim3(MDIM / 32, FDIM / 32, EDIM), dim3(32, 8)>>>(
        w2, FDIM, MDIM);
    // GEMM1: [CAP x M] @ w1t^T -> relu -> g_h (fp16 hi/lo)
    mma_gemm_kernel<MDIM, FDIM, true>
        <<<dim3(FDIM / BN, CAP / BM, EDIM), 256, GEMM_DSMEM>>>();
    // GEMM2: [CAP x F] @ w2t^T -> g_eo (fp32)
    mma_gemm_kernel<FDIM, MDIM, false>
        <<<dim3(MDIM / BN, CAP / BM, EDIM), 256, GEMM_DSMEM>>>();
    combine_kernel<<<SDIM, 256>>>(out);
}

// round 17
// speedup vs baseline: 4.9027x; 1.4687x over previous
#include <cuda_runtime.h>
#include <cuda_fp16.h>
#include <math.h>
#include <stdint.h>

// Problem constants (fixed shapes for MOELayer_53772990545994)
#define SDIM 4096      // S = B*T tokens
#define MDIM 1024      // model dim
#define EDIM 8         // experts
#define FDIM 4096      // ffn dim
#define CAP  1024      // capacity = 2*S/E

// ======================= helpers ===========================================
__device__ __forceinline__ uint32_t smem_u32(const void* p) {
    uint32_t a;
    asm("{ .reg .u64 t; cvta.to.shared.u64 t, %1; cvt.u32.u64 %0, t; }"
        : "=r"(a) : "l"(p));
    return a;
}
__device__ __forceinline__ void cp_async16(uint32_t saddr, const void* g) {
    asm volatile("cp.async.cg.shared.global [%0], [%1], 16;"
                 :: "r"(saddr), "l"(g) : "memory");
}
#define CP_COMMIT() asm volatile("cp.async.commit_group;" ::: "memory")
#define CP_WAIT1()  asm volatile("cp.async.wait_group 1;" ::: "memory")

__device__ __forceinline__ void ldsm_x4(uint32_t* r, uint32_t a) {
    asm volatile("ldmatrix.sync.aligned.m8n8.x4.shared.b16 {%0,%1,%2,%3}, [%4];"
                 : "=r"(r[0]), "=r"(r[1]), "=r"(r[2]), "=r"(r[3]) : "r"(a));
}
// fp16 inputs, fp32 accumulate
__device__ __forceinline__ void mma16816(float* c, const uint32_t* a, const uint32_t* b) {
    asm volatile("mma.sync.aligned.m16n8k16.row.col.f32.f16.f16.f32 "
                 "{%0,%1,%2,%3}, {%4,%5,%6,%7}, {%8,%9}, {%0,%1,%2,%3};"
                 : "+f"(c[0]), "+f"(c[1]), "+f"(c[2]), "+f"(c[3])
                 : "r"(a[0]), "r"(a[1]), "r"(a[2]), "r"(a[3]),
                   "r"(b[0]), "r"(b[1]));
}

// ======================= scratch (device globals) ===========================
// NOTE: only referenced from device code (host sees shadow addresses).
__device__ float g_gates[SDIM * EDIM];
__device__ int   g_idx1[SDIM], g_idx2[SDIM];
__device__ int   g_loc1[SDIM], g_loc2[SDIM];
__device__ float g_g1raw[SDIM], g_g2raw[SDIM];
__device__ float g_g1[SDIM], g_g2[SDIM];
__device__ int   g_slot[EDIM * CAP];
// single-fp16 operands everywhere (validated error model: each side ~2.8e-4)
__device__ __half g_xa [(size_t)EDIM * CAP * MDIM];
__device__ __half g_w1t[(size_t)EDIM * FDIM * MDIM];  // [e][f][m]
__device__ __half g_w2t[(size_t)EDIM * MDIM * FDIM];  // [e][m][f]
__device__ __half g_h  [(size_t)EDIM * CAP * FDIM];
__device__ float g_eo[(size_t)EDIM * CAP * MDIM];

// ======================= 1) gating ==========================================
__global__ void gate_kernel(const float* __restrict__ x,
                            const float* __restrict__ wg) {
    int warp = (blockIdx.x * blockDim.x + threadIdx.x) >> 5;
    int lane = threadIdx.x & 31;
    if (warp >= SDIM) return;
    const float* xr = x + (size_t)warp * MDIM;

    float acc[EDIM];
#pragma unroll
    for (int e = 0; e < EDIM; e++) acc[e] = 0.f;
    for (int m = lane; m < MDIM; m += 32) {
        float xv = xr[m];
        const float4* w4 = (const float4*)(wg + (size_t)m * EDIM);
        float4 a = w4[0], b = w4[1];
        acc[0] += xv * a.x; acc[1] += xv * a.y;
        acc[2] += xv * a.z; acc[3] += xv * a.w;
        acc[4] += xv * b.x; acc[5] += xv * b.y;
        acc[6] += xv * b.z; acc[7] += xv * b.w;
    }
#pragma unroll
    for (int o = 16; o > 0; o >>= 1)
#pragma unroll
        for (int e = 0; e < EDIM; e++)
            acc[e] += __shfl_xor_sync(0xffffffffu, acc[e], o);

    if (lane == 0) {
        float mx = acc[0];
#pragma unroll
        for (int e = 1; e < EDIM; e++) mx = fmaxf(mx, acc[e]);
        float p[EDIM], sum = 0.f;
#pragma unroll
        for (int e = 0; e < EDIM; e++) { p[e] = expf(acc[e] - mx); sum += p[e]; }
        float inv = 1.f / sum;
#pragma unroll
        for (int e = 0; e < EDIM; e++) {
            p[e] *= inv;
            g_gates[warp * EDIM + e] = p[e];
        }
        int i1 = 0;
#pragma unroll
        for (int e = 1; e < EDIM; e++) if (acc[e] > acc[i1]) i1 = e;
        int i2 = (i1 == 0) ? 1 : 0;
#pragma unroll
        for (int e = 0; e < EDIM; e++)
            if (e != i1 && acc[e] > acc[i2]) i2 = e;
        g_idx1[warp] = i1; g_idx2[warp] = i2;
        g_g1raw[warp] = p[i1]; g_g2raw[warp] = p[i2];
    }
}

// ======================= 2) scan (single block) =============================
__global__ void scan_kernel(float* laux_ptr) {
    __shared__ int   sCnt1[EDIM];
    __shared__ float sGsum[EDIM];
    int w    = threadIdx.x >> 5;
    int lane = threadIdx.x & 31;
    unsigned ltmask = (1u << lane) - 1u;

    int base = 0;
    for (int s0 = 0; s0 < SDIM; s0 += 32) {
        int s = s0 + lane;
        bool m = (g_idx1[s] == w);
        unsigned bal = __ballot_sync(0xffffffffu, m);
        if (m) g_loc1[s] = base + __popc(bal & ltmask);
        base += __popc(bal);
    }
    if (lane == 0) sCnt1[w] = base;
    __syncthreads();

    int base2 = sCnt1[w];
    for (int s0 = 0; s0 < SDIM; s0 += 32) {
        int s = s0 + lane;
        bool m = (g_idx2[s] == w);
        unsigned bal = __ballot_sync(0xffffffffu, m);
        if (m) g_loc2[s] = base2 + __popc(bal & ltmask);
        base2 += __popc(bal);
    }

    float acc = 0.f;
    for (int s = lane; s < SDIM; s += 32) acc += g_gates[s * EDIM + w];
#pragma unroll
    for (int o = 16; o > 0; o >>= 1) acc += __shfl_xor_sync(0xffffffffu, acc, o);
    if (lane == 0) sGsum[w] = acc;
    __syncthreads();

    if (threadIdx.x == 0 && laux_ptr != nullptr) {
        float l = 0.f;
#pragma unroll
        for (int e = 0; e < EDIM; e++) l += sGsum[e] * (float)sCnt1[e];
        *laux_ptr = l * (float)EDIM / ((float)SDIM * (float)SDIM);
    }
}

// ======================= 3) slot init + finalize ============================
__global__ void init_slot_kernel() {
    int i = blockIdx.x * blockDim.x + threadIdx.x;
    if (i < EDIM * CAP) g_slot[i] = -1;
}

__global__ void finalize_kernel() {
    int s = blockIdx.x * blockDim.x + threadIdx.x;
    if (s >= SDIM) return;
    int l1 = g_loc1[s], l2 = g_loc2[s];
    int i1 = g_idx1[s], i2 = g_idx2[s];
    bool k1 = (l1 < CAP), k2 = (l2 < CAP);
    float g1s = k1 ? g_g1raw[s] : 0.f;
    float g2s = k2 ? g_g2raw[s] : 0.f;
    float den = g1s + g2s;
    if (den < 1e-9f) den = 1e-9f;
    g_g1[s] = g1s / den;
    g_g2[s] = g2s / den;
    if (k1) g_slot[i1 * CAP + l1] = s;
    if (k2) g_slot[i2 * CAP + l2] = s;
}

// ======================= 4) convert + gather x into fp16 ====================
__global__ void convert_x_kernel(const float* __restrict__ x) {
    int slot = blockIdx.x;        // 0..8191
    int t = threadIdx.x;          // 256 threads * 4 elems
    int tok = g_slot[slot];
    float4 v = make_float4(0.f, 0.f, 0.f, 0.f);
    if (tok >= 0) v = ((const float4*)(x + (size_t)tok * MDIM))[t];
    __half h[4];
    h[0] = __float2half_rn(v.x); h[1] = __float2half_rn(v.y);
    h[2] = __float2half_rn(v.z); h[3] = __float2half_rn(v.w);
    size_t off = (size_t)slot * MDIM + t * 4;
    *(uint2*)&g_xa[off] = *(uint2*)h;
}

// ======================= 5) weight transpose (single fp16) ==================
// in: [E][R][Cc] fp32 -> g_wXt: [E][Cc][R] fp16.  WHICH: 1 -> w1t, 2 -> w2t.
template<int WHICH>
__global__ void transpose_split_kernel(const float* __restrict__ in,
                                       int R, int Cc) {
    __half* oh = (WHICH == 1) ? g_w1t : g_w2t;
    __shared__ float t[32][33];
    int e = blockIdx.z;
    int c0 = blockIdx.x * 32, r0 = blockIdx.y * 32;
    const float* ip = in + (size_t)e * R * Cc;
    for (int i = threadIdx.y; i < 32; i += 8)
        t[i][threadIdx.x] = ip[(size_t)(r0 + i) * Cc + c0 + threadIdx.x];
    __syncthreads();
    size_t ob = (size_t)e * R * Cc;
    for (int i = threadIdx.y; i < 32; i += 8) {
        float v = t[threadIdx.x][i];
        size_t o = ob + (size_t)(c0 + i) * R + r0 + threadIdx.x;
        oh[o] = __float2half_rn(v);
    }
}

// ======================= 6) fp16 HMMA GEMM (mma.sync) =======================
// C[128x128] per CTA = A[128xK] @ B[128xK]^T, plain fp16 operands.
// 8 warps (2x4), warp tile 64x32, m16n8k16 HMMA, ldmatrix.x4 fragments.
// BK=64 chunks, 3-stage cp.async pipeline, one __syncthreads per chunk.
// 110592 B dyn smem + <=128 regs -> 2 CTAs/SM (16 warps, 4/SMSP).
#define BM 128
#define BN 128
#define BK 64
#define NSTAGE 3
#define SROWB 144
#define A_BYTES (128 * SROWB)            // 18432
#define B_BYTES (128 * SROWB)            // 18432
#define STAGE_BYTES (A_BYTES + B_BYTES)  // 36864
#define B_SOFF A_BYTES
#define GEMM_DSMEM (NSTAGE * STAGE_BYTES) // 110592

template<int KDIM, int NTOT, bool FFN1>
__global__ __launch_bounds__(256, 2) void mma_gemm_kernel() {
    extern __shared__ char smbuf[];
    const int tid  = threadIdx.x;
    const int wid  = tid >> 5;
    const int lane = tid & 31;
    const int e    = blockIdx.z;
    const int row0 = blockIdx.y * BM;
    const int col0 = blockIdx.x * BN;
    const int KI   = KDIM / BK;       // chunks

    const int wm = (wid >> 2) * 64;   // warp row offset (2 groups of 64)
    const int wn = (wid & 3) * 32;    // warp col offset (4 groups of 32)
    const int lq = lane >> 2;         // 0..7
    const int lr = lane & 3;          // 0..3

    uint32_t sbase = smem_u32(smbuf);

    // device-side symbol resolution
    const __half* Ap = FFN1 ? g_xa  : g_h;
    const __half* Bp = FFN1 ? g_w1t : g_w2t;

    const __half* Ab = Ap + ((size_t)e * CAP  + row0) * KDIM;
    const __half* Bb = Bp + ((size_t)e * NTOT + col0) * KDIM;

    // chunk p: load A, B tiles (128x64 fp16 each)
    auto prefetch = [&](int p) {
        int kk = p * BK;
        uint32_t sb = sbase + (uint32_t)(p % NSTAGE) * STAGE_BYTES;
#pragma unroll
        for (int c = tid; c < 2048; c += 256) {
            int r = (c >> 3) & 127;
            int q = c & 7;
            uint32_t so = (uint32_t)(r * SROWB + q * 16);
            size_t go = (size_t)r * KDIM + kk + q * 8;
            if (c < 1024) cp_async16(sb + so,          Ab + go);
            else          cp_async16(sb + B_SOFF + so, Bb + go);
        }
    };

    float acc[4][4][4];
#pragma unroll
    for (int i = 0; i < 4; i++)
#pragma unroll
        for (int j = 0; j < 4; j++)
#pragma unroll
            for (int k = 0; k < 4; k++) acc[i][j][k] = 0.f;

    prefetch(0); CP_COMMIT();
    prefetch(1); CP_COMMIT();

    // per-thread intra-fragment offsets
    const int a_row  = lane & 15;
    const int a_half = (lane >> 4) << 4;
    const int b_grp  = lane >> 3;           // 0..3
    const int b_row  = (b_grp >> 1) * 8 + (lane & 7);
    const int b_half = (b_grp & 1) << 4;

    for (int i = 0; i < KI; i++) {
        CP_WAIT1();             // in-order completion => chunk i resident
        __syncthreads();        // all warps done reading stage (i-1)%3
        if (i + 2 < KI) prefetch(i + 2);
        CP_COMMIT();

        uint32_t sb = sbase + (uint32_t)(i % NSTAGE) * STAGE_BYTES;
#pragma unroll
        for (int ks = 0; ks < 4; ks++) {
            uint32_t a[4][4], bf[2][4];
#pragma unroll
            for (int mt = 0; mt < 4; mt++) {
                uint32_t addr = sb + (uint32_t)(wm + mt * 16 + a_row) * SROWB
                              + ks * 32 + a_half;
                ldsm_x4(a[mt], addr);
            }
#pragma unroll
            for (int np = 0; np < 2; np++) {   // covers nt=2np, 2np+1
                uint32_t addr = sb + B_SOFF
                              + (uint32_t)(wn + np * 16 + b_row) * SROWB
                              + ks * 32 + b_half;
                ldsm_x4(bf[np], addr);
            }
#pragma unroll
            for (int mt = 0; mt < 4; mt++)
#pragma unroll
                for (int nt = 0; nt < 4; nt++)
                    mma16816(acc[mt][nt], a[mt], &bf[nt >> 1][(nt & 1) * 2]);
        }
    }

    // epilogue: c0/c1 at (row=lq, col=lr*2), c2/c3 at row lq+8
#pragma unroll
    for (int mt = 0; mt < 4; mt++) {
#pragma unroll
        for (int half = 0; half < 2; half++) {
            int grow = row0 + wm + mt * 16 + lq + half * 8;
            size_t rowg = (size_t)e * CAP + grow;
#pragma unroll
            for (int nt = 0; nt < 4; nt++) {
                float v0 = acc[mt][nt][half * 2 + 0];
                float v1 = acc[mt][nt][half * 2 + 1];
                int gcol = col0 + wn + nt * 8 + lr * 2;
                if (FFN1) {
                    v0 = fmaxf(v0, 0.f); v1 = fmaxf(v1, 0.f);
                    __half2 hv = __halves2half2(__float2half_rn(v0),
                                                __float2half_rn(v1));
                    *(__half2*)&g_h[rowg * FDIM + gcol] = hv;
                } else {
                    float2 o; o.x = v0; o.y = v1;
                    *(float2*)&g_eo[rowg * MDIM + gcol] = o;
                }
            }
        }
    }
}

// ======================= 7) combine =========================================
__global__ void combine_kernel(float* __restrict__ out) {
    int s = blockIdx.x;
    int t = threadIdx.x;
    float g1 = g_g1[s], g2 = g_g2[s];
    int i1 = g_idx1[s], i2 = g_idx2[s];
    int l1 = g_loc1[s], l2 = g_loc2[s];
    bool k1 = (l1 < CAP), k2 = (l2 < CAP);

    float4 r = make_float4(0.f, 0.f, 0.f, 0.f);
    if (k1) {
        const float4* p = (const float4*)(g_eo + ((size_t)i1 * CAP + l1) * MDIM);
        float4 v = p[t];
        r.x += g1 * v.x; r.y += g1 * v.y; r.z += g1 * v.z; r.w += g1 * v.w;
    }
    if (k2) {
        const float4* p = (const float4*)(g_eo + ((size_t)i2 * CAP + l2) * MDIM);
        float4 v = p[t];
        r.x += g2 * v.x; r.y += g2 * v.y; r.z += g2 * v.z; r.w += g2 * v.w;
    }
    ((float4*)(out + (size_t)s * MDIM))[t] = r;
}

// ======================= launch =============================================
extern "C" void kernel_launch(void* const* d_in, const int* in_sizes, int n_in,
                              void* d_out, int out_size) {
    const float* x  = (const float*)d_in[0];
    const float* wg = (const float*)d_in[1];
    const float* w1 = (const float*)d_in[2];
    const float* w2 = (const float*)d_in[3];
    float* out = (float*)d_out;
    float* laux_ptr = (out_size > SDIM * MDIM) ? (out + (size_t)SDIM * MDIM) : nullptr;

    // opt into >48KB dynamic smem (idempotent; called every launch, no guards)
    cudaFuncSetAttribute(mma_gemm_kernel<MDIM, FDIM, true>,
                         cudaFuncAttributeMaxDynamicSharedMemorySize, GEMM_DSMEM);
    cudaFuncSetAttribute(mma_gemm_kernel<FDIM, MDIM, false>,
                         cudaFuncAttributeMaxDynamicSharedMemorySize, GEMM_DSMEM);

    gate_kernel<<<SDIM / 8, 256>>>(x, wg);
    scan_kernel<<<1, 256>>>(laux_ptr);
    init_slot_kernel<<<(EDIM * CAP + 255) / 256, 256>>>();
    finalize_kernel<<<SDIM / 256, 256>>>();
    convert_x_kernel<<<EDIM * CAP, 256>>>(x);
    // w1 [e][M][F] -> g_w1t [e][F][M] fp16
    transpose_split_kernel<1><<<dim3(FDIM / 32, MDIM / 32, EDIM), dim3(32, 8)>>>(
        w1, MDIM, FDIM);
    // w2 [e][F][M] -> g_w2t [e][M][F] fp16
    transpose_split_kernel<2><<<dim3(MDIM / 32, FDIM / 32, EDIM), dim3(32, 8)>>>(
        w2, FDIM, MDIM);
    // GEMM1: [CAP x M] @ w1t^T -> relu -> g_h (fp16)
    mma_gemm_kernel<MDIM, FDIM, true>
        <<<dim3(FDIM / BN, CAP / BM, EDIM), 256, GEMM_DSMEM>>>();
    // GEMM2: [CAP x F] @ w2t^T -> g_eo (fp32)
    mma_gemm_kernel<FDIM, MDIM, false>
        <<<dim3(MDIM / BN, CAP / BM, EDIM), 256, GEMM_DSMEM>>>();
    combine_kernel<<<SDIM, 256>>>(out);
}